// round 3
// baseline (speedup 1.0000x reference)
#include <cuda_runtime.h>
#include <math.h>
#include <stdint.h>

// ---------------- problem constants ----------------
#define TT      4096            // B*S tokens
#define HH      3584            // hidden
#define NHEADS  28
#define NKVH    4
#define GROUP   7
#define DH      128
#define QKVO    4608            // (28 + 2*4) * 128
#define SEQ     1024
#define NBATCH  4
#define KROW    512             // NKV*D, cache row per slot
#define CACHE_HALF 4194304      // NB*BS*NKV*D = 8192*512
#define OUT_ELEMS  14680064     // TT*HH
#define SCALE   0.088388347648318447f   // 1/sqrt(128)

// ---------------- scratch (device globals; no allocation) ----------------
__device__ float g_qkv[(size_t)TT * QKVO];   // qkv projection output (rope applied in place on q)
__device__ float g_ctx[(size_t)TT * HH];     // attention context output
__device__ float g_k[(size_t)TT * KROW];     // contiguous rope'd K for attention
__device__ float g_v[(size_t)TT * KROW];     // contiguous V for attention

// =====================================================================
// SGEMM  C[M,N] = A[M,K] * B[N,K]^T (+ bias[N])      (NT, K contiguous)
// BM=BN=128, BK=8, 256 threads, 8x8 micro-tile
// =====================================================================
template<int BIAS>
__global__ void __launch_bounds__(256) sgemm_nt(const float* __restrict__ A,
                                                const float* __restrict__ B,
                                                const float* __restrict__ bias,
                                                float* __restrict__ C,
                                                int M, int N, int K)
{
    __shared__ float As[8][128];
    __shared__ float Bs[8][128];
    const int m0 = blockIdx.y * 128;
    const int n0 = blockIdx.x * 128;
    const int tid = threadIdx.x;
    const int tx = tid & 15;          // 0..15  (N dir)
    const int ty = tid >> 4;          // 0..15  (M dir)
    const int lrow = tid >> 1;        // 0..127
    const int lk   = (tid & 1) * 4;   // 0 or 4

    const float* Ap = A + (size_t)(m0 + lrow) * K + lk;
    const float* Bp = B + (size_t)(n0 + lrow) * K + lk;

    float acc[8][8];
#pragma unroll
    for (int i = 0; i < 8; i++)
#pragma unroll
        for (int j = 0; j < 8; j++) acc[i][j] = 0.f;

    float4 a4 = *(const float4*)(Ap);
    float4 b4 = *(const float4*)(Bp);

    for (int k0 = 0; k0 < K; k0 += 8) {
        As[lk + 0][lrow] = a4.x; As[lk + 1][lrow] = a4.y;
        As[lk + 2][lrow] = a4.z; As[lk + 3][lrow] = a4.w;
        Bs[lk + 0][lrow] = b4.x; Bs[lk + 1][lrow] = b4.y;
        Bs[lk + 2][lrow] = b4.z; Bs[lk + 3][lrow] = b4.w;
        __syncthreads();
        if (k0 + 8 < K) {
            a4 = *(const float4*)(Ap + k0 + 8);
            b4 = *(const float4*)(Bp + k0 + 8);
        }
#pragma unroll
        for (int kk = 0; kk < 8; kk++) {
            float ar[8], br[8];
            *(float4*)(ar)     = *(const float4*)&As[kk][ty * 8];
            *(float4*)(ar + 4) = *(const float4*)&As[kk][ty * 8 + 4];
            *(float4*)(br)     = *(const float4*)&Bs[kk][tx * 8];
            *(float4*)(br + 4) = *(const float4*)&Bs[kk][tx * 8 + 4];
#pragma unroll
            for (int i = 0; i < 8; i++)
#pragma unroll
                for (int j = 0; j < 8; j++)
                    acc[i][j] += ar[i] * br[j];
        }
        __syncthreads();
    }

    float bv[8];
    if (BIAS) {
#pragma unroll
        for (int j = 0; j < 8; j++) bv[j] = bias[n0 + tx * 8 + j];
    }
#pragma unroll
    for (int i = 0; i < 8; i++) {
        float* Cp = C + (size_t)(m0 + ty * 8 + i) * N + n0 + tx * 8;
        if (BIAS) {
#pragma unroll
            for (int j = 0; j < 8; j++) acc[i][j] += bv[j];
        }
        *(float4*)(Cp)     = make_float4(acc[i][0], acc[i][1], acc[i][2], acc[i][3]);
        *(float4*)(Cp + 4) = make_float4(acc[i][4], acc[i][5], acc[i][6], acc[i][7]);
    }
}

// =====================================================================
// RoPE (in place on q inside g_qkv) + rope'd K / V into contiguous
// scratch (for attention) and into the cache region at slot_mapping[t].
// hh: 0..27 q-heads, 28..31 k-heads, 32..35 v-heads. i = pair 0..63.
// =====================================================================
__global__ void rope_scatter(const int* __restrict__ positions,
                             const int* __restrict__ slot_mapping,
                             float* __restrict__ cache_out)
{
    const int idx = blockIdx.x * blockDim.x + threadIdx.x;
    const int total = TT * 36 * 64;
    if (idx >= total) return;
    const int i  = idx & 63;
    const int hh = (idx >> 6) % 36;
    const int t  = idx / (36 * 64);

    if (hh < 32) {
        const float pos = (float)positions[t];
        // inv_freq = 10000^(-i/64) = exp2(-i * log2(10000)/64)
        const float inv = exp2f(-(float)i * (13.287712379549449f / 64.0f));
        const float ang = pos * inv;
        float s, c;
        sincosf(ang, &s, &c);
        if (hh < 28) {
            float* p = g_qkv + (size_t)t * QKVO + hh * DH;
            const float x1 = p[i], x2 = p[i + 64];
            p[i]      = x1 * c - x2 * s;
            p[i + 64] = x2 * c + x1 * s;
        } else {
            const int kvh = hh - 28;
            const float* p = g_qkv + (size_t)t * QKVO + NHEADS * DH + kvh * DH;
            const float x1 = p[i], x2 = p[i + 64];
            const float r1 = x1 * c - x2 * s;
            const float r2 = x2 * c + x1 * s;
            float* kc = g_k + (size_t)t * KROW + kvh * DH;
            kc[i]      = r1;
            kc[i + 64] = r2;
            const int slot = slot_mapping[t];
            float* dst = cache_out + (size_t)slot * KROW + kvh * DH;
            dst[i]      = r1;
            dst[i + 64] = r2;
        }
    } else {
        const int kvh = hh - 32;
        const float* p = g_qkv + (size_t)t * QKVO + (NHEADS + NKVH) * DH + kvh * DH;
        const float v1 = p[i], v2 = p[i + 64];
        float* vc = g_v + (size_t)t * KROW + kvh * DH;
        vc[i]      = v1;
        vc[i + 64] = v2;
        const int slot = slot_mapping[t];
        float* dst = cache_out + (size_t)CACHE_HALF + (size_t)slot * KROW + kvh * DH;
        dst[i]      = v1;
        dst[i + 64] = v2;
    }
}

// =====================================================================
// Flash attention, fp32, causal. One block = (64 q rows, one head, one batch).
// 128 threads = 4 warps; warp w owns q rows w*16..w*16+15.
// Lane j owns score columns {j, j+32} and output dims {j, j+32, j+64, j+96}.
// =====================================================================
__global__ void __launch_bounds__(128) attn_fwd(const float* __restrict__ kcache,
                                                const float* __restrict__ vcache)
{
    extern __shared__ float sm[];
    float* Qs = sm;                       // [64][128]
    float* Ks = sm + 64 * 128;            // [64][132]  (pad vs bank conflicts)
    float* Vs = Ks + 64 * 132;            // [64][128]
    float* Ps = Vs + 64 * 128;            // [4][16][68]

    const int qt = blockIdx.x, h = blockIdx.y, b = blockIdx.z;
    const int kvh  = h / GROUP;
    const int tid  = threadIdx.x;
    const int w    = tid >> 5;
    const int lane = tid & 31;

    // load Q tile
    for (int i = tid; i < 64 * 32; i += 128) {
        const int r = i >> 5, dq = i & 31;
        *(float4*)&Qs[r * 128 + dq * 4] =
            *(const float4*)&g_qkv[(size_t)(b * SEQ + qt * 64 + r) * QKVO + h * DH + dq * 4];
    }

    float o0[16], o1[16], o2[16], o3[16], mi[16], li[16];
#pragma unroll
    for (int q = 0; q < 16; q++) {
        o0[q] = o1[q] = o2[q] = o3[q] = 0.f;
        mi[q] = -1e30f; li[q] = 0.f;
    }

    float* Pw = Ps + w * 16 * 68;

    for (int j = 0; j <= qt; j++) {
        __syncthreads();   // Qs ready (iter 0) / previous tile consumed
        for (int i = tid; i < 64 * 32; i += 128) {
            const int c = i >> 5, dq = i & 31;
            const size_t base = (size_t)(b * SEQ + j * 64 + c) * KROW + kvh * DH + dq * 4;
            *(float4*)&Ks[c * 132 + dq * 4] = *(const float4*)&kcache[base];
            *(float4*)&Vs[c * 128 + dq * 4] = *(const float4*)&vcache[base];
        }
        __syncthreads();

        // ---- QK^T : lane computes cols {lane, lane+32} for 16 rows ----
        float s0[16], s1[16];
#pragma unroll
        for (int q = 0; q < 16; q++) { s0[q] = 0.f; s1[q] = 0.f; }
        for (int dq = 0; dq < 32; dq++) {
            const float4 k0 = *(const float4*)&Ks[lane * 132 + dq * 4];
            const float4 k1 = *(const float4*)&Ks[(lane + 32) * 132 + dq * 4];
#pragma unroll
            for (int q = 0; q < 16; q++) {
                const float4 q4 = *(const float4*)&Qs[(w * 16 + q) * 128 + dq * 4];
                s0[q] += q4.x * k0.x + q4.y * k0.y + q4.z * k0.z + q4.w * k0.w;
                s1[q] += q4.x * k1.x + q4.y * k1.y + q4.z * k1.z + q4.w * k1.w;
            }
        }

        // ---- online softmax ----
#pragma unroll
        for (int q = 0; q < 16; q++) {
            const int r = w * 16 + q;
            float v0 = s0[q] * SCALE, v1 = s1[q] * SCALE;
            if (j == qt) {
                if (lane > r)      v0 = -1e30f;
                if (lane + 32 > r) v1 = -1e30f;
            }
            float mt = fmaxf(v0, v1);
#pragma unroll
            for (int off = 16; off; off >>= 1)
                mt = fmaxf(mt, __shfl_xor_sync(0xffffffffu, mt, off));
            const float mnew = fmaxf(mi[q], mt);
            const float p0 = __expf(v0 - mnew);
            const float p1 = __expf(v1 - mnew);
            const float corr = __expf(mi[q] - mnew);
            mi[q] = mnew;
            float ps = p0 + p1;
#pragma unroll
            for (int off = 16; off; off >>= 1)
                ps += __shfl_xor_sync(0xffffffffu, ps, off);
            li[q] = li[q] * corr + ps;
            o0[q] *= corr; o1[q] *= corr; o2[q] *= corr; o3[q] *= corr;
            Pw[q * 68 + lane]      = p0;
            Pw[q * 68 + lane + 32] = p1;
        }
        __syncwarp();

        // ---- P @ V : lane owns dims {lane, +32, +64, +96} ----
        for (int c = 0; c < 64; c++) {
            const float v0 = Vs[c * 128 + lane];
            const float v1 = Vs[c * 128 + lane + 32];
            const float v2 = Vs[c * 128 + lane + 64];
            const float v3 = Vs[c * 128 + lane + 96];
#pragma unroll
            for (int q = 0; q < 16; q++) {
                const float p = Pw[q * 68 + c];
                o0[q] += p * v0; o1[q] += p * v1; o2[q] += p * v2; o3[q] += p * v3;
            }
        }
        __syncwarp();
    }

    // ---- write ctx ----
#pragma unroll
    for (int q = 0; q < 16; q++) {
        const int r = w * 16 + q;
        const size_t t = (size_t)(b * SEQ + qt * 64 + r);
        const float inv = 1.f / li[q];
        float* cp = g_ctx + t * HH + h * DH;
        cp[lane]      = o0[q] * inv;
        cp[lane + 32] = o1[q] * inv;
        cp[lane + 64] = o2[q] * inv;
        cp[lane + 96] = o3[q] * inv;
    }
}

// =====================================================================
// launch
// =====================================================================
extern "C" void kernel_launch(void* const* d_in, const int* in_sizes, int n_in,
                              void* d_out, int out_size)
{
    // resolve inputs by element count (unique per tensor; positions is the
    // FIRST 4096-element int input, slot_mapping the SECOND)
    const float* hs = nullptr;
    const float* wqkv = nullptr;
    const float* bqkv = nullptr;
    const float* wo = nullptr;
    const float* kvc = nullptr;
    const int* positions = nullptr;
    const int* slot_mapping = nullptr;

    for (int i = 0; i < n_in; i++) {
        switch (in_sizes[i]) {
            case 14680064: hs   = (const float*)d_in[i]; break;  // hidden_states
            case 16515072: wqkv = (const float*)d_in[i]; break;  // w_qkv
            case 4608:     bqkv = (const float*)d_in[i]; break;  // b_qkv
            case 12845056: wo   = (const float*)d_in[i]; break;  // w_o
            case 8388608:  kvc  = (const float*)d_in[i]; break;  // kv_cache
            case 4096:
                if (!positions)         positions    = (const int*)d_in[i];
                else if (!slot_mapping) slot_mapping = (const int*)d_in[i];
                break;
            default: break;
        }
    }

    float* out       = (float*)d_out;
    float* cache_out = out + OUT_ELEMS;

    float* qkv_ptr = nullptr;
    float* ctx_ptr = nullptr;
    float* k_ptr = nullptr;
    float* v_ptr = nullptr;
    cudaGetSymbolAddress((void**)&qkv_ptr, g_qkv);
    cudaGetSymbolAddress((void**)&ctx_ptr, g_ctx);
    cudaGetSymbolAddress((void**)&k_ptr, g_k);
    cudaGetSymbolAddress((void**)&v_ptr, g_v);

    const int attn_smem = (64 * 128 + 64 * 132 + 64 * 128 + 4 * 16 * 68) * 4;
    cudaFuncSetAttribute(attn_fwd, cudaFuncAttributeMaxDynamicSharedMemorySize, attn_smem);

    // 1) QKV projection: [4096,4608] = hs[4096,3584] @ w_qkv^T + b
    sgemm_nt<1><<<dim3(QKVO / 128, TT / 128), 256>>>(hs, wqkv, bqkv, qkv_ptr, TT, QKVO, HH);

    // 2) copy input cache into output cache region (untouched slots keep input)
    cudaMemcpyAsync(cache_out, kvc, (size_t)2 * CACHE_HALF * sizeof(float),
                    cudaMemcpyDeviceToDevice);

    // 3) RoPE q (in place), rope'd k + v -> contiguous scratch and cache scatter
    {
        const int total = TT * 36 * 64;
        rope_scatter<<<(total + 255) / 256, 256>>>(positions, slot_mapping, cache_out);
    }

    // 4) causal GQA flash attention -> g_ctx
    attn_fwd<<<dim3(SEQ / 64, NHEADS, NBATCH), 128, attn_smem>>>(k_ptr, v_ptr);

    // 5) output projection: out[4096,3584] = ctx @ w_o^T
    sgemm_nt<0><<<dim3(HH / 128, TT / 128), 256>>>(ctx_ptr, wo, nullptr, out, TT, HH, HH);

    (void)out_size;
}

// round 5
// speedup vs baseline: 1.8188x; 1.8188x over previous
#include <cuda_runtime.h>
#include <cuda_bf16.h>
#include <math.h>
#include <stdint.h>

// ---------------- problem constants ----------------
#define TT      4096            // B*S tokens
#define HH      3584            // hidden
#define NHEADS  28
#define NKVH    4
#define GROUP   7
#define DH      128
#define QKVO    4608            // (28 + 2*4) * 128
#define SEQ     1024
#define NBATCH  4
#define KROW    512             // NKV*D, cache row per slot
#define CACHE_HALF 4194304      // NB*BS*NKV*D = 8192*512
#define OUT_ELEMS  14680064     // TT*HH
#define SCALE   0.088388347648318447f   // 1/sqrt(128)
#define KT      3584            // GEMM K (both projections)
#define PASSLEN (KT / 32)       // 112 k-stages of 32 per pass
#define KSTEPS  (3 * PASSLEN)   // 336 stages total (3 bf16 passes)

// ---------------- scratch (device globals; no allocation) ----------------
__device__ float g_qkv[(size_t)TT * QKVO];
__device__ float g_ctx[(size_t)TT * HH];
__device__ float g_k[(size_t)TT * KROW];
__device__ float g_v[(size_t)TT * KROW];
__device__ __nv_bfloat16 g_ah[(size_t)TT * HH];
__device__ __nv_bfloat16 g_al[(size_t)TT * HH];
__device__ __nv_bfloat16 g_wqh[(size_t)QKVO * HH];
__device__ __nv_bfloat16 g_wql[(size_t)QKVO * HH];
__device__ __nv_bfloat16 g_woh[(size_t)HH * HH];
__device__ __nv_bfloat16 g_wol[(size_t)HH * HH];
__device__ __nv_bfloat16 g_ch[(size_t)TT * HH];
__device__ __nv_bfloat16 g_cl[(size_t)TT * HH];

// ---------------- PTX helpers (baseline features only) ----------------
__device__ __forceinline__ uint32_t smem_to_u32(const void* p) {
    uint32_t a;
    asm("{ .reg .u64 t; cvta.to.shared.u64 t, %1; cvt.u32.u64 %0, t; }" : "=r"(a) : "l"(p));
    return a;
}
__device__ __forceinline__ void cpasync16(uint32_t dst, const void* src) {
    asm volatile("cp.async.cg.shared.global [%0], [%1], 16;" :: "r"(dst), "l"(src));
}
#define CP_COMMIT() asm volatile("cp.async.commit_group;" ::: "memory")
#define CP_WAIT1()  asm volatile("cp.async.wait_group 1;" ::: "memory")

__device__ __forceinline__ void ldsm4(uint32_t& r0, uint32_t& r1, uint32_t& r2, uint32_t& r3,
                                      uint32_t a) {
    asm volatile("ldmatrix.sync.aligned.m8n8.x4.shared.b16 {%0,%1,%2,%3}, [%4];"
                 : "=r"(r0), "=r"(r1), "=r"(r2), "=r"(r3) : "r"(a));
}
__device__ __forceinline__ void mma16816(float* c, const uint32_t* a, const uint32_t* b) {
    asm volatile("mma.sync.aligned.m16n8k16.row.col.f32.bf16.bf16.f32 "
                 "{%0,%1,%2,%3}, {%4,%5,%6,%7}, {%8,%9}, {%0,%1,%2,%3};"
                 : "+f"(c[0]), "+f"(c[1]), "+f"(c[2]), "+f"(c[3])
                 : "r"(a[0]), "r"(a[1]), "r"(a[2]), "r"(a[3]), "r"(b[0]), "r"(b[1]));
}

// swizzled offset inside a [rows][32 bf16] tile (64B rows): conflict-free for
// both the 4-lane-per-row cp.async store phase and each 8-address ldmatrix phase
__device__ __forceinline__ uint32_t swz(int row, int chunk) {
    return (uint32_t)(row * 64 + ((chunk ^ ((row >> 1) & 3)) << 4));
}

// =====================================================================
// fp32 -> bf16 hi/lo split
// =====================================================================
__global__ void conv_split(const float* __restrict__ x,
                           __nv_bfloat16* __restrict__ hi,
                           __nv_bfloat16* __restrict__ lo, int n4)
{
    const int i = blockIdx.x * blockDim.x + threadIdx.x;
    if (i >= n4) return;
    const float4 v = ((const float4*)x)[i];
    __nv_bfloat16 h0 = __float2bfloat16_rn(v.x);
    __nv_bfloat16 h1 = __float2bfloat16_rn(v.y);
    __nv_bfloat16 h2 = __float2bfloat16_rn(v.z);
    __nv_bfloat16 h3 = __float2bfloat16_rn(v.w);
    __nv_bfloat16 l0 = __float2bfloat16_rn(v.x - __bfloat162float(h0));
    __nv_bfloat16 l1 = __float2bfloat16_rn(v.y - __bfloat162float(h1));
    __nv_bfloat16 l2 = __float2bfloat16_rn(v.z - __bfloat162float(h2));
    __nv_bfloat16 l3 = __float2bfloat16_rn(v.w - __bfloat162float(h3));
    __nv_bfloat162* H = (__nv_bfloat162*)(hi + (size_t)i * 4);
    __nv_bfloat162* L = (__nv_bfloat162*)(lo + (size_t)i * 4);
    H[0] = __nv_bfloat162(h0, h1); H[1] = __nv_bfloat162(h2, h3);
    L[0] = __nv_bfloat162(l0, l1); L[1] = __nv_bfloat162(l2, l3);
}

// =====================================================================
// HMMA bf16x3 GEMM  C[M,Nt] = A[M,KT]*B[Nt,KT]^T (+bias)
// 128x128 CTA tile, 8 warps (4M x 2N), warp tile 32x64, BK=32.
// 3-stage cp.async pipeline; logical K = 3*KT (hi*hi, hi*lo, lo*hi).
// =====================================================================
template<int BIAS>
__global__ void __launch_bounds__(256, 2) tc_gemm(const __nv_bfloat16* __restrict__ ah,
                                                  const __nv_bfloat16* __restrict__ al,
                                                  const __nv_bfloat16* __restrict__ bh,
                                                  const __nv_bfloat16* __restrict__ bl,
                                                  const float* __restrict__ bias,
                                                  float* __restrict__ C, int Nt)
{
    __shared__ __align__(1024) char smem[3 * 16384];   // 3 stages x (A 8K + B 8K)
    const uint32_t smem_u = smem_to_u32(smem);

    const int tid  = threadIdx.x;
    const int wid  = tid >> 5;
    const int lane = tid & 31;
    const int wm   = wid & 3;          // warp M index (0..3)
    const int wn   = wid >> 2;         // warp N index (0..1)
    const int n0   = blockIdx.x * 128;
    const int m0   = blockIdx.y * 128;

    // --- loader lane mapping: 4 chunks of 16B per thread (2 A + 2 B) ---
    // chunk id q: row = q>>2 (0..127), chunk = q&3
    const int q0 = tid, q1 = tid + 256;
    const int ar0 = q0 >> 2, ac0 = q0 & 3;
    const int ar1 = q1 >> 2, ac1 = q1 & 3;
    const uint32_t sA0 = swz(ar0, ac0), sA1 = swz(ar1, ac1);

    // --- ldmatrix lane address components ---
    const int g = lane >> 3, j = lane & 7;
    uint32_t a_off[2][2];   // [mt][kc]
#pragma unroll
    for (int mt = 0; mt < 2; mt++)
#pragma unroll
        for (int kc = 0; kc < 2; kc++) {
            const int row = wm * 32 + mt * 16 + (g & 1) * 8 + j;
            a_off[mt][kc] = swz(row, kc * 2 + (g >> 1));
        }
    uint32_t b_off[4][2];   // [nt16][kc]
#pragma unroll
    for (int nt = 0; nt < 4; nt++)
#pragma unroll
        for (int kc = 0; kc < 2; kc++) {
            const int row = wn * 64 + nt * 16 + (g >> 1) * 8 + j;
            b_off[nt][kc] = swz(row, kc * 2 + (g & 1));
        }

    float acc[2][8][4];
#pragma unroll
    for (int mi = 0; mi < 2; mi++)
#pragma unroll
        for (int ni = 0; ni < 8; ni++)
#pragma unroll
            for (int k = 0; k < 4; k++) acc[mi][ni][k] = 0.f;

    auto load_stage = [&](int s, int buf) {
        const int pass = s / PASSLEN;
        const int k0   = (s % PASSLEN) * 32;
        const __nv_bfloat16* Ap = (pass < 2) ? ah : al;
        const __nv_bfloat16* Bp = (pass == 1) ? bl : bh;
        const uint32_t Au = smem_u + buf * 16384;
        const uint32_t Bu = Au + 8192;
        cpasync16(Au + sA0, Ap + (size_t)(m0 + ar0) * KT + k0 + ac0 * 8);
        cpasync16(Au + sA1, Ap + (size_t)(m0 + ar1) * KT + k0 + ac1 * 8);
        cpasync16(Bu + sA0, Bp + (size_t)(n0 + ar0) * KT + k0 + ac0 * 8);
        cpasync16(Bu + sA1, Bp + (size_t)(n0 + ar1) * KT + k0 + ac1 * 8);
    };

    load_stage(0, 0); CP_COMMIT();
    load_stage(1, 1); CP_COMMIT();

#pragma unroll 1
    for (int s = 0; s < KSTEPS; s++) {
        CP_WAIT1();
        __syncthreads();
        const int buf = s % 3;
        if (s + 2 < KSTEPS) load_stage(s + 2, (s + 2) % 3);
        CP_COMMIT();

        const uint32_t Au = smem_u + buf * 16384;
        const uint32_t Bu = Au + 8192;
#pragma unroll
        for (int kc = 0; kc < 2; kc++) {
            uint32_t a[2][4];
            ldsm4(a[0][0], a[0][1], a[0][2], a[0][3], Au + a_off[0][kc]);
            ldsm4(a[1][0], a[1][1], a[1][2], a[1][3], Au + a_off[1][kc]);
            uint32_t b[8][2];
#pragma unroll
            for (int nt = 0; nt < 4; nt++)
                ldsm4(b[2 * nt][0], b[2 * nt][1], b[2 * nt + 1][0], b[2 * nt + 1][1],
                      Bu + b_off[nt][kc]);
#pragma unroll
            for (int mi = 0; mi < 2; mi++)
#pragma unroll
                for (int ni = 0; ni < 8; ni++)
                    mma16816(acc[mi][ni], a[mi], b[ni]);
        }
    }

    // --- epilogue: direct fp32 stores ---
    const int r0 = m0 + wm * 32 + (lane >> 2);
    const int c0 = n0 + wn * 64 + (lane & 3) * 2;
#pragma unroll
    for (int mi = 0; mi < 2; mi++)
#pragma unroll
        for (int ni = 0; ni < 8; ni++) {
            const int row = r0 + mi * 16;
            const int col = c0 + ni * 8;
            float b0 = 0.f, b1 = 0.f;
            if (BIAS) { b0 = bias[col]; b1 = bias[col + 1]; }
            *(float2*)&C[(size_t)row * Nt + col] =
                make_float2(acc[mi][ni][0] + b0, acc[mi][ni][1] + b1);
            *(float2*)&C[(size_t)(row + 8) * Nt + col] =
                make_float2(acc[mi][ni][2] + b0, acc[mi][ni][3] + b1);
        }
}

// =====================================================================
// RoPE (in place on q) + rope'd K / V -> contiguous scratch + cache scatter
// =====================================================================
__global__ void rope_scatter(const int* __restrict__ positions,
                             const int* __restrict__ slot_mapping,
                             float* __restrict__ cache_out)
{
    const int idx = blockIdx.x * blockDim.x + threadIdx.x;
    const int total = TT * 36 * 64;
    if (idx >= total) return;
    const int i  = idx & 63;
    const int hh = (idx >> 6) % 36;
    const int t  = idx / (36 * 64);

    if (hh < 32) {
        const float pos = (float)positions[t];
        const float inv = exp2f(-(float)i * (13.287712379549449f / 64.0f));
        const float ang = pos * inv;
        float s, c;
        sincosf(ang, &s, &c);
        if (hh < 28) {
            float* p = g_qkv + (size_t)t * QKVO + hh * DH;
            const float x1 = p[i], x2 = p[i + 64];
            p[i]      = x1 * c - x2 * s;
            p[i + 64] = x2 * c + x1 * s;
        } else {
            const int kvh = hh - 28;
            const float* p = g_qkv + (size_t)t * QKVO + NHEADS * DH + kvh * DH;
            const float x1 = p[i], x2 = p[i + 64];
            const float r1 = x1 * c - x2 * s;
            const float r2 = x2 * c + x1 * s;
            float* kc = g_k + (size_t)t * KROW + kvh * DH;
            kc[i]      = r1;
            kc[i + 64] = r2;
            const int slot = slot_mapping[t];
            float* dst = cache_out + (size_t)slot * KROW + kvh * DH;
            dst[i]      = r1;
            dst[i + 64] = r2;
        }
    } else {
        const int kvh = hh - 32;
        const float* p = g_qkv + (size_t)t * QKVO + (NHEADS + NKVH) * DH + kvh * DH;
        const float v1 = p[i], v2 = p[i + 64];
        float* vc = g_v + (size_t)t * KROW + kvh * DH;
        vc[i]      = v1;
        vc[i + 64] = v2;
        const int slot = slot_mapping[t];
        float* dst = cache_out + (size_t)CACHE_HALF + (size_t)slot * KROW + kvh * DH;
        dst[i]      = v1;
        dst[i + 64] = v2;
    }
}

// =====================================================================
// Flash attention, fp32, causal (unchanged from round 3)
// =====================================================================
__global__ void __launch_bounds__(128) attn_fwd(const float* __restrict__ kcache,
                                                const float* __restrict__ vcache)
{
    extern __shared__ float sm[];
    float* Qs = sm;
    float* Ks = sm + 64 * 128;
    float* Vs = Ks + 64 * 132;
    float* Ps = Vs + 64 * 128;

    const int qt = blockIdx.x, h = blockIdx.y, b = blockIdx.z;
    const int kvh  = h / GROUP;
    const int tid  = threadIdx.x;
    const int w    = tid >> 5;
    const int lane = tid & 31;

    for (int i = tid; i < 64 * 32; i += 128) {
        const int r = i >> 5, dq = i & 31;
        *(float4*)&Qs[r * 128 + dq * 4] =
            *(const float4*)&g_qkv[(size_t)(b * SEQ + qt * 64 + r) * QKVO + h * DH + dq * 4];
    }

    float o0[16], o1[16], o2[16], o3[16], mi[16], li[16];
#pragma unroll
    for (int q = 0; q < 16; q++) {
        o0[q] = o1[q] = o2[q] = o3[q] = 0.f;
        mi[q] = -1e30f; li[q] = 0.f;
    }

    float* Pw = Ps + w * 16 * 68;

    for (int j = 0; j <= qt; j++) {
        __syncthreads();
        for (int i = tid; i < 64 * 32; i += 128) {
            const int c = i >> 5, dq = i & 31;
            const size_t base = (size_t)(b * SEQ + j * 64 + c) * KROW + kvh * DH + dq * 4;
            *(float4*)&Ks[c * 132 + dq * 4] = *(const float4*)&kcache[base];
            *(float4*)&Vs[c * 128 + dq * 4] = *(const float4*)&vcache[base];
        }
        __syncthreads();

        float s0[16], s1[16];
#pragma unroll
        for (int q = 0; q < 16; q++) { s0[q] = 0.f; s1[q] = 0.f; }
        for (int dq = 0; dq < 32; dq++) {
            const float4 k0 = *(const float4*)&Ks[lane * 132 + dq * 4];
            const float4 k1 = *(const float4*)&Ks[(lane + 32) * 132 + dq * 4];
#pragma unroll
            for (int q = 0; q < 16; q++) {
                const float4 q4 = *(const float4*)&Qs[(w * 16 + q) * 128 + dq * 4];
                s0[q] += q4.x * k0.x + q4.y * k0.y + q4.z * k0.z + q4.w * k0.w;
                s1[q] += q4.x * k1.x + q4.y * k1.y + q4.z * k1.z + q4.w * k1.w;
            }
        }

#pragma unroll
        for (int q = 0; q < 16; q++) {
            const int r = w * 16 + q;
            float v0 = s0[q] * SCALE, v1 = s1[q] * SCALE;
            if (j == qt) {
                if (lane > r)      v0 = -1e30f;
                if (lane + 32 > r) v1 = -1e30f;
            }
            float mt = fmaxf(v0, v1);
#pragma unroll
            for (int off = 16; off; off >>= 1)
                mt = fmaxf(mt, __shfl_xor_sync(0xffffffffu, mt, off));
            const float mnew = fmaxf(mi[q], mt);
            const float p0 = __expf(v0 - mnew);
            const float p1 = __expf(v1 - mnew);
            const float corr = __expf(mi[q] - mnew);
            mi[q] = mnew;
            float ps = p0 + p1;
#pragma unroll
            for (int off = 16; off; off >>= 1)
                ps += __shfl_xor_sync(0xffffffffu, ps, off);
            li[q] = li[q] * corr + ps;
            o0[q] *= corr; o1[q] *= corr; o2[q] *= corr; o3[q] *= corr;
            Pw[q * 68 + lane]      = p0;
            Pw[q * 68 + lane + 32] = p1;
        }
        __syncwarp();

        for (int c = 0; c < 64; c++) {
            const float v0 = Vs[c * 128 + lane];
            const float v1 = Vs[c * 128 + lane + 32];
            const float v2 = Vs[c * 128 + lane + 64];
            const float v3 = Vs[c * 128 + lane + 96];
#pragma unroll
            for (int q = 0; q < 16; q++) {
                const float p = Pw[q * 68 + c];
                o0[q] += p * v0; o1[q] += p * v1; o2[q] += p * v2; o3[q] += p * v3;
            }
        }
        __syncwarp();
    }

#pragma unroll
    for (int q = 0; q < 16; q++) {
        const int r = w * 16 + q;
        const size_t t = (size_t)(b * SEQ + qt * 64 + r);
        const float inv = 1.f / li[q];
        float* cp = g_ctx + t * HH + h * DH;
        cp[lane]      = o0[q] * inv;
        cp[lane + 32] = o1[q] * inv;
        cp[lane + 64] = o2[q] * inv;
        cp[lane + 96] = o3[q] * inv;
    }
}

// =====================================================================
// launch
// =====================================================================
extern "C" void kernel_launch(void* const* d_in, const int* in_sizes, int n_in,
                              void* d_out, int out_size)
{
    const float* hs = nullptr;
    const float* wqkv = nullptr;
    const float* bqkv = nullptr;
    const float* wo = nullptr;
    const float* kvc = nullptr;
    const int* positions = nullptr;
    const int* slot_mapping = nullptr;

    for (int i = 0; i < n_in; i++) {
        switch (in_sizes[i]) {
            case 14680064: hs   = (const float*)d_in[i]; break;
            case 16515072: wqkv = (const float*)d_in[i]; break;
            case 4608:     bqkv = (const float*)d_in[i]; break;
            case 12845056: wo   = (const float*)d_in[i]; break;
            case 8388608:  kvc  = (const float*)d_in[i]; break;
            case 4096:
                if (!positions)         positions    = (const int*)d_in[i];
                else if (!slot_mapping) slot_mapping = (const int*)d_in[i];
                break;
            default: break;
        }
    }

    float* out       = (float*)d_out;
    float* cache_out = out + OUT_ELEMS;

    float *qkv_ptr, *ctx_ptr, *k_ptr, *v_ptr;
    __nv_bfloat16 *ah, *al, *wqh, *wql, *woh, *wol, *ch, *cl;
    cudaGetSymbolAddress((void**)&qkv_ptr, g_qkv);
    cudaGetSymbolAddress((void**)&ctx_ptr, g_ctx);
    cudaGetSymbolAddress((void**)&k_ptr, g_k);
    cudaGetSymbolAddress((void**)&v_ptr, g_v);
    cudaGetSymbolAddress((void**)&ah, g_ah);
    cudaGetSymbolAddress((void**)&al, g_al);
    cudaGetSymbolAddress((void**)&wqh, g_wqh);
    cudaGetSymbolAddress((void**)&wql, g_wql);
    cudaGetSymbolAddress((void**)&woh, g_woh);
    cudaGetSymbolAddress((void**)&wol, g_wol);
    cudaGetSymbolAddress((void**)&ch, g_ch);
    cudaGetSymbolAddress((void**)&cl, g_cl);

    const int attn_smem = (64 * 128 + 64 * 132 + 64 * 128 + 4 * 16 * 68) * 4;
    cudaFuncSetAttribute(attn_fwd, cudaFuncAttributeMaxDynamicSharedMemorySize, attn_smem);

    // 0) bf16 hi/lo splits of activations + weights
    conv_split<<<(TT * HH / 4 + 255) / 256, 256>>>(hs, ah, al, TT * HH / 4);
    conv_split<<<(QKVO * HH / 4 + 255) / 256, 256>>>(wqkv, wqh, wql, QKVO * HH / 4);
    conv_split<<<(HH * HH / 4 + 255) / 256, 256>>>(wo, woh, wol, HH * HH / 4);

    // 1) QKV projection (HMMA bf16x3)
    tc_gemm<1><<<dim3(QKVO / 128, TT / 128), 256>>>(ah, al, wqh, wql, bqkv, qkv_ptr, QKVO);

    // 2) copy input cache into output cache region
    cudaMemcpyAsync(cache_out, kvc, (size_t)2 * CACHE_HALF * sizeof(float),
                    cudaMemcpyDeviceToDevice);

    // 3) RoPE + scatter
    {
        const int total = TT * 36 * 64;
        rope_scatter<<<(total + 255) / 256, 256>>>(positions, slot_mapping, cache_out);
    }

    // 4) causal GQA flash attention -> g_ctx
    attn_fwd<<<dim3(SEQ / 64, NHEADS, NBATCH), 128, attn_smem>>>(k_ptr, v_ptr);

    // 5) ctx split + output projection (HMMA bf16x3)
    conv_split<<<(TT * HH / 4 + 255) / 256, 256>>>(ctx_ptr, ch, cl, TT * HH / 4);
    tc_gemm<0><<<dim3(HH / 128, TT / 128), 256>>>(ch, cl, woh, wol, nullptr, out, HH);

    (void)out_size;
}

// round 7
// speedup vs baseline: 2.9508x; 1.6224x over previous
#include <cuda_runtime.h>
#include <cuda_bf16.h>
#include <cuda_fp16.h>
#include <math.h>
#include <stdint.h>

// ---------------- problem constants ----------------
#define TT      4096            // B*S tokens
#define HH      3584            // hidden
#define NHEADS  28
#define NKVH    4
#define GROUP   7
#define DH      128
#define QKVO    4608            // (28 + 2*4) * 128
#define SEQ     1024
#define NBATCH  4
#define KROW    512             // NKV*D, cache row per slot
#define CACHE_HALF 4194304      // NB*BS*NKV*D
#define OUT_ELEMS  14680064     // TT*HH
#define SCALE   0.088388347648318447f   // 1/sqrt(128)
#define KT      3584            // GEMM K (both projections)
#define PASSLEN (KT / 32)
#define KSTEPS  (3 * PASSLEN)

// ---------------- scratch (device globals; no allocation) ----------------
__device__ float g_qkv[(size_t)TT * QKVO];
__device__ __nv_bfloat16 g_ah[(size_t)TT * HH];
__device__ __nv_bfloat16 g_al[(size_t)TT * HH];
__device__ __nv_bfloat16 g_wqh[(size_t)QKVO * HH];
__device__ __nv_bfloat16 g_wql[(size_t)QKVO * HH];
__device__ __nv_bfloat16 g_woh[(size_t)HH * HH];
__device__ __nv_bfloat16 g_wol[(size_t)HH * HH];
__device__ __nv_bfloat16 g_ch[(size_t)TT * HH];     // ctx hi (written by attention)
__device__ __nv_bfloat16 g_cl[(size_t)TT * HH];     // ctx lo
// attention operands
__device__ __nv_bfloat16 g_qh[(size_t)TT * HH];     // rope'd Q hi  [T][28*128]
__device__ __nv_bfloat16 g_ql[(size_t)TT * HH];     // rope'd Q lo
__device__ __nv_bfloat16 g_kh[(size_t)TT * KROW];   // rope'd K hi  [T][4*128]
__device__ __nv_bfloat16 g_kl[(size_t)TT * KROW];
__device__ __half        g_vh[(size_t)TT * KROW];   // V hi (f16)
__device__ __half        g_vl[(size_t)TT * KROW];   // V lo (f16)

// ---------------- PTX helpers (baseline features only) ----------------
__device__ __forceinline__ uint32_t smem_to_u32(const void* p) {
    uint32_t a;
    asm("{ .reg .u64 t; cvta.to.shared.u64 t, %1; cvt.u32.u64 %0, t; }" : "=r"(a) : "l"(p));
    return a;
}
__device__ __forceinline__ void cpasync16(uint32_t dst, const void* src) {
    asm volatile("cp.async.cg.shared.global [%0], [%1], 16;" :: "r"(dst), "l"(src));
}
#define CP_COMMIT() asm volatile("cp.async.commit_group;" ::: "memory")
#define CP_WAIT1()  asm volatile("cp.async.wait_group 1;" ::: "memory")
#define CP_WAIT0()  asm volatile("cp.async.wait_group 0;" ::: "memory")

__device__ __forceinline__ void ldsm4(uint32_t& r0, uint32_t& r1, uint32_t& r2, uint32_t& r3,
                                      uint32_t a) {
    asm volatile("ldmatrix.sync.aligned.m8n8.x4.shared.b16 {%0,%1,%2,%3}, [%4];"
                 : "=r"(r0), "=r"(r1), "=r"(r2), "=r"(r3) : "r"(a));
}
__device__ __forceinline__ void ldsm4t(uint32_t& r0, uint32_t& r1, uint32_t& r2, uint32_t& r3,
                                       uint32_t a) {
    asm volatile("ldmatrix.sync.aligned.m8n8.x4.trans.shared.b16 {%0,%1,%2,%3}, [%4];"
                 : "=r"(r0), "=r"(r1), "=r"(r2), "=r"(r3) : "r"(a));
}
__device__ __forceinline__ void mma_bf16(float* c, const uint32_t* a, const uint32_t* b) {
    asm volatile("mma.sync.aligned.m16n8k16.row.col.f32.bf16.bf16.f32 "
                 "{%0,%1,%2,%3}, {%4,%5,%6,%7}, {%8,%9}, {%0,%1,%2,%3};"
                 : "+f"(c[0]), "+f"(c[1]), "+f"(c[2]), "+f"(c[3])
                 : "r"(a[0]), "r"(a[1]), "r"(a[2]), "r"(a[3]), "r"(b[0]), "r"(b[1]));
}
__device__ __forceinline__ void mma_f16(float* c, const uint32_t* a, uint32_t b0, uint32_t b1) {
    asm volatile("mma.sync.aligned.m16n8k16.row.col.f32.f16.f16.f32 "
                 "{%0,%1,%2,%3}, {%4,%5,%6,%7}, {%8,%9}, {%0,%1,%2,%3};"
                 : "+f"(c[0]), "+f"(c[1]), "+f"(c[2]), "+f"(c[3])
                 : "r"(a[0]), "r"(a[1]), "r"(a[2]), "r"(a[3]), "r"(b0), "r"(b1));
}
__device__ __forceinline__ float ex2f(float x) {
    float y; asm("ex2.approx.ftz.f32 %0, %1;" : "=f"(y) : "f"(x)); return y;
}

// 64B-row tile swizzle (GEMM, 32 bf16/row)
__device__ __forceinline__ uint32_t swz(int row, int chunk) {
    return (uint32_t)(row * 64 + ((chunk ^ ((row >> 1) & 3)) << 4));
}
// 256B-row tile swizzle (attention, 128 b16/row, 16 chunks of 16B)
__device__ __forceinline__ uint32_t swz256(int row, int chunk) {
    return (uint32_t)(row * 256 + ((chunk ^ (row & 7)) << 4));
}

// =====================================================================
// fp32 -> bf16 hi/lo split
// =====================================================================
__global__ void conv_split(const float* __restrict__ x,
                           __nv_bfloat16* __restrict__ hi,
                           __nv_bfloat16* __restrict__ lo, int n4)
{
    const int i = blockIdx.x * blockDim.x + threadIdx.x;
    if (i >= n4) return;
    const float4 v = ((const float4*)x)[i];
    __nv_bfloat16 h0 = __float2bfloat16_rn(v.x);
    __nv_bfloat16 h1 = __float2bfloat16_rn(v.y);
    __nv_bfloat16 h2 = __float2bfloat16_rn(v.z);
    __nv_bfloat16 h3 = __float2bfloat16_rn(v.w);
    __nv_bfloat16 l0 = __float2bfloat16_rn(v.x - __bfloat162float(h0));
    __nv_bfloat16 l1 = __float2bfloat16_rn(v.y - __bfloat162float(h1));
    __nv_bfloat16 l2 = __float2bfloat16_rn(v.z - __bfloat162float(h2));
    __nv_bfloat16 l3 = __float2bfloat16_rn(v.w - __bfloat162float(h3));
    __nv_bfloat162* H = (__nv_bfloat162*)(hi + (size_t)i * 4);
    __nv_bfloat162* L = (__nv_bfloat162*)(lo + (size_t)i * 4);
    H[0] = __nv_bfloat162(h0, h1); H[1] = __nv_bfloat162(h2, h3);
    L[0] = __nv_bfloat162(l0, l1); L[1] = __nv_bfloat162(l2, l3);
}

// =====================================================================
// HMMA bf16x3 GEMM (unchanged from round 5)
// =====================================================================
template<int BIAS>
__global__ void __launch_bounds__(256, 2) tc_gemm(const __nv_bfloat16* __restrict__ ah,
                                                  const __nv_bfloat16* __restrict__ al,
                                                  const __nv_bfloat16* __restrict__ bh,
                                                  const __nv_bfloat16* __restrict__ bl,
                                                  const float* __restrict__ bias,
                                                  float* __restrict__ C, int Nt)
{
    __shared__ __align__(1024) char smem[3 * 16384];
    const uint32_t smem_u = smem_to_u32(smem);

    const int tid  = threadIdx.x;
    const int wid  = tid >> 5;
    const int lane = tid & 31;
    const int wm   = wid & 3;
    const int wn   = wid >> 2;
    const int n0   = blockIdx.x * 128;
    const int m0   = blockIdx.y * 128;

    const int q0 = tid, q1 = tid + 256;
    const int ar0 = q0 >> 2, ac0 = q0 & 3;
    const int ar1 = q1 >> 2, ac1 = q1 & 3;
    const uint32_t sA0 = swz(ar0, ac0), sA1 = swz(ar1, ac1);

    const int g = lane >> 3, j = lane & 7;
    uint32_t a_off[2][2];
#pragma unroll
    for (int mt = 0; mt < 2; mt++)
#pragma unroll
        for (int kc = 0; kc < 2; kc++) {
            const int row = wm * 32 + mt * 16 + (g & 1) * 8 + j;
            a_off[mt][kc] = swz(row, kc * 2 + (g >> 1));
        }
    uint32_t b_off[4][2];
#pragma unroll
    for (int nt = 0; nt < 4; nt++)
#pragma unroll
        for (int kc = 0; kc < 2; kc++) {
            const int row = wn * 64 + nt * 16 + (g >> 1) * 8 + j;
            b_off[nt][kc] = swz(row, kc * 2 + (g & 1));
        }

    float acc[2][8][4];
#pragma unroll
    for (int mi = 0; mi < 2; mi++)
#pragma unroll
        for (int ni = 0; ni < 8; ni++)
#pragma unroll
            for (int k = 0; k < 4; k++) acc[mi][ni][k] = 0.f;

    auto load_stage = [&](int s, int buf) {
        const int pass = s / PASSLEN;
        const int k0   = (s % PASSLEN) * 32;
        const __nv_bfloat16* Ap = (pass < 2) ? ah : al;
        const __nv_bfloat16* Bp = (pass == 1) ? bl : bh;
        const uint32_t Au = smem_u + buf * 16384;
        const uint32_t Bu = Au + 8192;
        cpasync16(Au + sA0, Ap + (size_t)(m0 + ar0) * KT + k0 + ac0 * 8);
        cpasync16(Au + sA1, Ap + (size_t)(m0 + ar1) * KT + k0 + ac1 * 8);
        cpasync16(Bu + sA0, Bp + (size_t)(n0 + ar0) * KT + k0 + ac0 * 8);
        cpasync16(Bu + sA1, Bp + (size_t)(n0 + ar1) * KT + k0 + ac1 * 8);
    };

    load_stage(0, 0); CP_COMMIT();
    load_stage(1, 1); CP_COMMIT();

#pragma unroll 1
    for (int s = 0; s < KSTEPS; s++) {
        CP_WAIT1();
        __syncthreads();
        const int buf = s % 3;
        if (s + 2 < KSTEPS) load_stage(s + 2, (s + 2) % 3);
        CP_COMMIT();

        const uint32_t Au = smem_u + buf * 16384;
        const uint32_t Bu = Au + 8192;
#pragma unroll
        for (int kc = 0; kc < 2; kc++) {
            uint32_t a[2][4];
            ldsm4(a[0][0], a[0][1], a[0][2], a[0][3], Au + a_off[0][kc]);
            ldsm4(a[1][0], a[1][1], a[1][2], a[1][3], Au + a_off[1][kc]);
            uint32_t b[8][2];
#pragma unroll
            for (int nt = 0; nt < 4; nt++)
                ldsm4(b[2 * nt][0], b[2 * nt][1], b[2 * nt + 1][0], b[2 * nt + 1][1],
                      Bu + b_off[nt][kc]);
#pragma unroll
            for (int mi = 0; mi < 2; mi++)
#pragma unroll
                for (int ni = 0; ni < 8; ni++)
                    mma_bf16(acc[mi][ni], a[mi], b[ni]);
        }
    }

    const int r0 = m0 + wm * 32 + (lane >> 2);
    const int c0 = n0 + wn * 64 + (lane & 3) * 2;
#pragma unroll
    for (int mi = 0; mi < 2; mi++)
#pragma unroll
        for (int ni = 0; ni < 8; ni++) {
            const int row = r0 + mi * 16;
            const int col = c0 + ni * 8;
            float b0 = 0.f, b1 = 0.f;
            if (BIAS) { b0 = bias[col]; b1 = bias[col + 1]; }
            *(float2*)&C[(size_t)row * Nt + col] =
                make_float2(acc[mi][ni][0] + b0, acc[mi][ni][1] + b1);
            *(float2*)&C[(size_t)(row + 8) * Nt + col] =
                make_float2(acc[mi][ni][2] + b0, acc[mi][ni][3] + b1);
        }
}

// =====================================================================
// RoPE: q -> bf16 hi/lo scratch; k -> fp32 cache + bf16 hi/lo;
//       v -> fp32 cache + f16 hi/lo
// =====================================================================
__global__ void rope_scatter(const int* __restrict__ positions,
                             const int* __restrict__ slot_mapping,
                             float* __restrict__ cache_out)
{
    const int idx = blockIdx.x * blockDim.x + threadIdx.x;
    const int total = TT * 36 * 64;
    if (idx >= total) return;
    const int i  = idx & 63;
    const int hh = (idx >> 6) % 36;
    const int t  = idx / (36 * 64);

    if (hh < 32) {
        const float pos = (float)positions[t];
        const float inv = exp2f(-(float)i * (13.287712379549449f / 64.0f));
        const float ang = pos * inv;
        float s, c;
        sincosf(ang, &s, &c);
        if (hh < 28) {
            const float* p = g_qkv + (size_t)t * QKVO + hh * DH;
            const float x1 = p[i], x2 = p[i + 64];
            const float r1 = x1 * c - x2 * s;
            const float r2 = x2 * c + x1 * s;
            const size_t o = (size_t)t * HH + hh * DH;
            __nv_bfloat16 h1 = __float2bfloat16_rn(r1);
            __nv_bfloat16 h2 = __float2bfloat16_rn(r2);
            g_qh[o + i]      = h1;
            g_qh[o + i + 64] = h2;
            g_ql[o + i]      = __float2bfloat16_rn(r1 - __bfloat162float(h1));
            g_ql[o + i + 64] = __float2bfloat16_rn(r2 - __bfloat162float(h2));
        } else {
            const int kvh = hh - 28;
            const float* p = g_qkv + (size_t)t * QKVO + NHEADS * DH + kvh * DH;
            const float x1 = p[i], x2 = p[i + 64];
            const float r1 = x1 * c - x2 * s;
            const float r2 = x2 * c + x1 * s;
            const size_t o = (size_t)t * KROW + kvh * DH;
            __nv_bfloat16 h1 = __float2bfloat16_rn(r1);
            __nv_bfloat16 h2 = __float2bfloat16_rn(r2);
            g_kh[o + i]      = h1;
            g_kh[o + i + 64] = h2;
            g_kl[o + i]      = __float2bfloat16_rn(r1 - __bfloat162float(h1));
            g_kl[o + i + 64] = __float2bfloat16_rn(r2 - __bfloat162float(h2));
            const int slot = slot_mapping[t];
            float* dst = cache_out + (size_t)slot * KROW + kvh * DH;
            dst[i]      = r1;
            dst[i + 64] = r2;
        }
    } else {
        const int kvh = hh - 32;
        const float* p = g_qkv + (size_t)t * QKVO + (NHEADS + NKVH) * DH + kvh * DH;
        const float v1 = p[i], v2 = p[i + 64];
        const size_t o = (size_t)t * KROW + kvh * DH;
        __half h1 = __float2half_rn(v1);
        __half h2 = __float2half_rn(v2);
        g_vh[o + i]      = h1;
        g_vh[o + i + 64] = h2;
        g_vl[o + i]      = __float2half_rn(v1 - __half2float(h1));
        g_vl[o + i + 64] = __float2half_rn(v2 - __half2float(h2));
        const int slot = slot_mapping[t];
        float* dst = cache_out + (size_t)CACHE_HALF + (size_t)slot * KROW + kvh * DH;
        dst[i]      = v1;
        dst[i + 64] = v2;
    }
}

// =====================================================================
// Tensor-core flash attention (causal, GQA).
// CTA = 64 q rows x head x batch; 4 warps, warp w -> rows w*16..w*16+15.
// QK: bf16 hi/lo 3-term; softmax fp32 (ex2.approx); PV: f16 P x f16 V hi/lo.
// Writes ctx directly as bf16 hi/lo for the O-projection.
// =====================================================================
__global__ void __launch_bounds__(128) attn_fwd_tc(
    __nv_bfloat16* __restrict__ ch_g, __nv_bfloat16* __restrict__ cl_g)
{
    extern __shared__ __align__(1024) char smem[];
    const uint32_t su = smem_to_u32(smem);
    const uint32_t Qh = su, Ql = su + 16384, Kh = su + 32768, Kl = su + 49152,
                   Vh = su + 65536, Vl = su + 81920;

    const int qt  = (gridDim.x - 1) - blockIdx.x;    // big tiles first
    const int h   = blockIdx.y, b = blockIdx.z;
    const int kvh = h / GROUP;
    const int tid = threadIdx.x, wid = tid >> 5, lane = tid & 31;
    const int g   = lane >> 3, jj = lane & 7;

    // loader mapping: conflict-free (8 consecutive lanes -> 8 consecutive rows)
    const int lrow = tid & 63, lc0 = (tid >> 6) * 8;

    // ---- Q tiles (hi+lo), loaded once ----
    {
        const size_t t = (size_t)(b * SEQ + qt * 64 + lrow);
        const __nv_bfloat16* gh = g_qh + t * HH + h * DH + lc0 * 8;
        const __nv_bfloat16* gl = g_ql + t * HH + h * DH + lc0 * 8;
#pragma unroll
        for (int i = 0; i < 8; i++) {
            cpasync16(Qh + swz256(lrow, lc0 + i), gh + i * 8);
            cpasync16(Ql + swz256(lrow, lc0 + i), gl + i * 8);
        }
    }
    CP_COMMIT();

    // ldmatrix address components
    const int arow = wid * 16 + (g & 1) * 8 + jj;   // A (Q / P rows)
    const int acb  = g >> 1;
    const int brow = (g >> 1) * 8 + jj;             // B non-trans (K rows)
    const int bcb  = g & 1;
    const int vrow = (g & 1) * 8 + jj;              // B trans (V rows)
    const int vcb  = g >> 1;

    float O[16][4];
#pragma unroll
    for (int nt = 0; nt < 16; nt++)
#pragma unroll
        for (int k = 0; k < 4; k++) O[nt][k] = 0.f;
    float m0 = -1e30f, m1 = -1e30f, l0 = 0.f, l1 = 0.f;
    const float K1 = SCALE * 1.4426950408889634f;   // fold log2(e)

#pragma unroll 1
    for (int j = 0; j <= qt; j++) {
        // ---- load K hi/lo (bf16) + V hi/lo (f16) tiles ----
        {
            const size_t t = (size_t)(b * SEQ + j * 64 + lrow);
            const __nv_bfloat16* kh = g_kh + t * KROW + kvh * DH + lc0 * 8;
            const __nv_bfloat16* kl = g_kl + t * KROW + kvh * DH + lc0 * 8;
            const __half* vh = g_vh + t * KROW + kvh * DH + lc0 * 8;
            const __half* vl = g_vl + t * KROW + kvh * DH + lc0 * 8;
#pragma unroll
            for (int i = 0; i < 8; i++) {
                const uint32_t so = swz256(lrow, lc0 + i);
                cpasync16(Kh + so, kh + i * 8);
                cpasync16(Kl + so, kl + i * 8);
                cpasync16(Vh + so, vh + i * 8);
                cpasync16(Vl + so, vl + i * 8);
            }
        }
        CP_COMMIT(); CP_WAIT0();
        __syncthreads();

        // ---- QK^T (3-term bf16 hi/lo) ----
        float sa[8][4];
#pragma unroll
        for (int nt = 0; nt < 8; nt++)
#pragma unroll
            for (int k = 0; k < 4; k++) sa[nt][k] = 0.f;

#pragma unroll
        for (int ds = 0; ds < 8; ds++) {
            uint32_t qhf[4], qlf[4];
            ldsm4(qhf[0], qhf[1], qhf[2], qhf[3], Qh + swz256(arow, ds * 2 + acb));
            ldsm4(qlf[0], qlf[1], qlf[2], qlf[3], Ql + swz256(arow, ds * 2 + acb));
#pragma unroll
            for (int p = 0; p < 4; p++) {
                uint32_t h0, h1, h2, h3, e0, e1, e2, e3;
                const uint32_t ko = swz256(p * 16 + brow, ds * 2 + bcb);
                ldsm4(h0, h1, h2, h3, Kh + ko);
                ldsm4(e0, e1, e2, e3, Kl + ko);
                {
                    uint32_t bb[2] = {h0, h1};
                    mma_bf16(sa[2 * p], qhf, bb);
                    uint32_t ll[2] = {e0, e1};
                    mma_bf16(sa[2 * p], qhf, ll);
                    mma_bf16(sa[2 * p], qlf, bb);
                }
                {
                    uint32_t bb[2] = {h2, h3};
                    mma_bf16(sa[2 * p + 1], qhf, bb);
                    uint32_t ll[2] = {e2, e3};
                    mma_bf16(sa[2 * p + 1], qhf, ll);
                    mma_bf16(sa[2 * p + 1], qlf, bb);
                }
            }
        }

        // ---- scale to log2 domain + causal mask ----
        const int row0 = wid * 16 + (lane >> 2);
#pragma unroll
        for (int nt = 0; nt < 8; nt++)
#pragma unroll
            for (int k = 0; k < 4; k++) sa[nt][k] *= K1;
        if (j == qt) {
#pragma unroll
            for (int nt = 0; nt < 8; nt++) {
                const int cb = nt * 8 + 2 * (lane & 3);
                if (cb > row0)         sa[nt][0] = -1e30f;
                if (cb + 1 > row0)     sa[nt][1] = -1e30f;
                if (cb > row0 + 8)     sa[nt][2] = -1e30f;
                if (cb + 1 > row0 + 8) sa[nt][3] = -1e30f;
            }
        }

        // ---- online softmax ----
        float mt0 = -1e30f, mt1 = -1e30f;
#pragma unroll
        for (int nt = 0; nt < 8; nt++) {
            mt0 = fmaxf(mt0, fmaxf(sa[nt][0], sa[nt][1]));
            mt1 = fmaxf(mt1, fmaxf(sa[nt][2], sa[nt][3]));
        }
        mt0 = fmaxf(mt0, __shfl_xor_sync(0xffffffffu, mt0, 1));
        mt0 = fmaxf(mt0, __shfl_xor_sync(0xffffffffu, mt0, 2));
        mt1 = fmaxf(mt1, __shfl_xor_sync(0xffffffffu, mt1, 1));
        mt1 = fmaxf(mt1, __shfl_xor_sync(0xffffffffu, mt1, 2));
        const float mn0 = fmaxf(m0, mt0), mn1 = fmaxf(m1, mt1);
        const float cr0 = ex2f(m0 - mn0), cr1 = ex2f(m1 - mn1);
        m0 = mn0; m1 = mn1;

        uint32_t p2[2][8];
        float s0 = 0.f, s1 = 0.f;
#pragma unroll
        for (int nt = 0; nt < 8; nt++) {
            const float e0 = ex2f(sa[nt][0] - m0);
            const float e1 = ex2f(sa[nt][1] - m0);
            const float e2 = ex2f(sa[nt][2] - m1);
            const float e3 = ex2f(sa[nt][3] - m1);
            s0 += e0 + e1; s1 += e2 + e3;
            p2[0][nt] = __half2_raw(__floats2half2_rn(e0, e1)).x |
                        ((uint32_t)__half2_raw(__floats2half2_rn(e0, e1)).y << 16);
            p2[1][nt] = __half2_raw(__floats2half2_rn(e2, e3)).x |
                        ((uint32_t)__half2_raw(__floats2half2_rn(e2, e3)).y << 16);
        }
        s0 += __shfl_xor_sync(0xffffffffu, s0, 1);
        s0 += __shfl_xor_sync(0xffffffffu, s0, 2);
        s1 += __shfl_xor_sync(0xffffffffu, s1, 1);
        s1 += __shfl_xor_sync(0xffffffffu, s1, 2);
        l0 = l0 * cr0 + s0;
        l1 = l1 * cr1 + s1;
#pragma unroll
        for (int nt = 0; nt < 16; nt++) {
            O[nt][0] *= cr0; O[nt][1] *= cr0;
            O[nt][2] *= cr1; O[nt][3] *= cr1;
        }

        // ---- P @ V (f16, V hi/lo 2-term) ----
#pragma unroll
        for (int ks = 0; ks < 4; ks++) {
            uint32_t af[4] = {p2[0][2 * ks], p2[1][2 * ks],
                              p2[0][2 * ks + 1], p2[1][2 * ks + 1]};
#pragma unroll
            for (int p = 0; p < 8; p++) {
                const uint32_t vo = swz256(ks * 16 + vrow, p * 2 + vcb);
                uint32_t v0, v1, v2, v3;
                ldsm4t(v0, v1, v2, v3, Vh + vo);
                mma_f16(O[2 * p],     af, v0, v1);
                mma_f16(O[2 * p + 1], af, v2, v3);
                ldsm4t(v0, v1, v2, v3, Vl + vo);
                mma_f16(O[2 * p],     af, v0, v1);
                mma_f16(O[2 * p + 1], af, v2, v3);
            }
        }
        __syncthreads();
    }

    // ---- epilogue: normalize, split to bf16 hi/lo, store ----
    const float il0 = 1.f / l0, il1 = 1.f / l1;
    const int row0 = wid * 16 + (lane >> 2);
    const size_t t0 = (size_t)(b * SEQ + qt * 64 + row0);
    const size_t t1 = t0 + 8;
#pragma unroll
    for (int nt = 0; nt < 16; nt++) {
        const int d = h * DH + nt * 8 + 2 * (lane & 3);
        {
            const float x0 = O[nt][0] * il0, x1 = O[nt][1] * il0;
            __nv_bfloat16 h0 = __float2bfloat16_rn(x0);
            __nv_bfloat16 h1 = __float2bfloat16_rn(x1);
            *(__nv_bfloat162*)&ch_g[t0 * HH + d] = __nv_bfloat162(h0, h1);
            *(__nv_bfloat162*)&cl_g[t0 * HH + d] = __nv_bfloat162(
                __float2bfloat16_rn(x0 - __bfloat162float(h0)),
                __float2bfloat16_rn(x1 - __bfloat162float(h1)));
        }
        {
            const float x0 = O[nt][2] * il1, x1 = O[nt][3] * il1;
            __nv_bfloat16 h0 = __float2bfloat16_rn(x0);
            __nv_bfloat16 h1 = __float2bfloat16_rn(x1);
            *(__nv_bfloat162*)&ch_g[t1 * HH + d] = __nv_bfloat162(h0, h1);
            *(__nv_bfloat162*)&cl_g[t1 * HH + d] = __nv_bfloat162(
                __float2bfloat16_rn(x0 - __bfloat162float(h0)),
                __float2bfloat16_rn(x1 - __bfloat162float(h1)));
        }
    }
}

// =====================================================================
// launch
// =====================================================================
extern "C" void kernel_launch(void* const* d_in, const int* in_sizes, int n_in,
                              void* d_out, int out_size)
{
    const float* hs = nullptr;
    const float* wqkv = nullptr;
    const float* bqkv = nullptr;
    const float* wo = nullptr;
    const float* kvc = nullptr;
    const int* positions = nullptr;
    const int* slot_mapping = nullptr;

    for (int i = 0; i < n_in; i++) {
        switch (in_sizes[i]) {
            case 14680064: hs   = (const float*)d_in[i]; break;
            case 16515072: wqkv = (const float*)d_in[i]; break;
            case 4608:     bqkv = (const float*)d_in[i]; break;
            case 12845056: wo   = (const float*)d_in[i]; break;
            case 8388608:  kvc  = (const float*)d_in[i]; break;
            case 4096:
                if (!positions)         positions    = (const int*)d_in[i];
                else if (!slot_mapping) slot_mapping = (const int*)d_in[i];
                break;
            default: break;
        }
    }

    float* out       = (float*)d_out;
    float* cache_out = out + OUT_ELEMS;

    float* qkv_ptr;
    __nv_bfloat16 *ah, *al, *wqh, *wql, *woh, *wol, *ch, *cl;
    cudaGetSymbolAddress((void**)&qkv_ptr, g_qkv);
    cudaGetSymbolAddress((void**)&ah, g_ah);
    cudaGetSymbolAddress((void**)&al, g_al);
    cudaGetSymbolAddress((void**)&wqh, g_wqh);
    cudaGetSymbolAddress((void**)&wql, g_wql);
    cudaGetSymbolAddress((void**)&woh, g_woh);
    cudaGetSymbolAddress((void**)&wol, g_wol);
    cudaGetSymbolAddress((void**)&ch, g_ch);
    cudaGetSymbolAddress((void**)&cl, g_cl);

    const int attn_smem = 6 * 16384;   // 96KB
    cudaFuncSetAttribute(attn_fwd_tc, cudaFuncAttributeMaxDynamicSharedMemorySize, attn_smem);

    // 0) bf16 hi/lo splits of activations + weights
    conv_split<<<(TT * HH / 4 + 255) / 256, 256>>>(hs, ah, al, TT * HH / 4);
    conv_split<<<(QKVO * HH / 4 + 255) / 256, 256>>>(wqkv, wqh, wql, QKVO * HH / 4);
    conv_split<<<(HH * HH / 4 + 255) / 256, 256>>>(wo, woh, wol, HH * HH / 4);

    // 1) QKV projection (HMMA bf16x3)
    tc_gemm<1><<<dim3(QKVO / 128, TT / 128), 256>>>(ah, al, wqh, wql, bqkv, qkv_ptr, QKVO);

    // 2) copy input cache into output cache region
    cudaMemcpyAsync(cache_out, kvc, (size_t)2 * CACHE_HALF * sizeof(float),
                    cudaMemcpyDeviceToDevice);

    // 3) RoPE + scatter + bf16/f16 operand prep
    {
        const int total = TT * 36 * 64;
        rope_scatter<<<(total + 255) / 256, 256>>>(positions, slot_mapping, cache_out);
    }

    // 4) tensor-core causal GQA flash attention -> ctx bf16 hi/lo
    attn_fwd_tc<<<dim3(SEQ / 64, NHEADS, NBATCH), 128, attn_smem>>>(ch, cl);

    // 5) output projection (HMMA bf16x3)
    tc_gemm<0><<<dim3(HH / 128, TT / 128), 256>>>(ch, cl, woh, wol, nullptr, out, HH);

    (void)out_size;
}

// round 10
// speedup vs baseline: 3.3579x; 1.1379x over previous
#include <cuda_runtime.h>
#include <cuda_bf16.h>
#include <cuda_fp16.h>
#include <math.h>
#include <stdint.h>

// ---------------- problem constants ----------------
#define TT      4096            // B*S tokens
#define HH      3584            // hidden
#define NHEADS  28
#define NKVH    4
#define GROUP   7
#define DH      128
#define QKVO    4608            // (28 + 2*4) * 128
#define SEQ     1024
#define NBATCH  4
#define KROW    512             // NKV*D, cache row per slot
#define CACHE_HALF 4194304      // NB*BS*NKV*D
#define OUT_ELEMS  14680064     // TT*HH
#define SCALE   0.088388347648318447f   // 1/sqrt(128)
#define KT      3584            // GEMM K (both projections)
#define PASSLEN64 (KT / 64)     // 56 k-stages of 64 per pass
#define KSTEPS64  (3 * PASSLEN64)  // 168 stages total (3 bf16 passes)

// ---------------- scratch (device globals; no allocation) ----------------
__device__ float g_qkv[(size_t)TT * QKVO];
__device__ __nv_bfloat16 g_ah[(size_t)TT * HH];
__device__ __nv_bfloat16 g_al[(size_t)TT * HH];
__device__ __nv_bfloat16 g_wqh[(size_t)QKVO * HH];
__device__ __nv_bfloat16 g_wql[(size_t)QKVO * HH];
__device__ __nv_bfloat16 g_woh[(size_t)HH * HH];
__device__ __nv_bfloat16 g_wol[(size_t)HH * HH];
__device__ __nv_bfloat16 g_ch[(size_t)TT * HH];     // ctx hi (written by attention)
__device__ __nv_bfloat16 g_cl[(size_t)TT * HH];     // ctx lo
// attention operands
__device__ __nv_bfloat16 g_qh[(size_t)TT * HH];
__device__ __nv_bfloat16 g_ql[(size_t)TT * HH];
__device__ __nv_bfloat16 g_kh[(size_t)TT * KROW];
__device__ __nv_bfloat16 g_kl[(size_t)TT * KROW];
__device__ __half        g_vh[(size_t)TT * KROW];
__device__ __half        g_vl[(size_t)TT * KROW];

// ---------------- PTX helpers (baseline features only) ----------------
__device__ __forceinline__ uint32_t smem_to_u32(const void* p) {
    uint32_t a;
    asm("{ .reg .u64 t; cvta.to.shared.u64 t, %1; cvt.u32.u64 %0, t; }" : "=r"(a) : "l"(p));
    return a;
}
__device__ __forceinline__ void cpasync16(uint32_t dst, const void* src) {
    asm volatile("cp.async.cg.shared.global [%0], [%1], 16;" :: "r"(dst), "l"(src));
}
#define CP_COMMIT() asm volatile("cp.async.commit_group;" ::: "memory")
#define CP_WAIT1()  asm volatile("cp.async.wait_group 1;" ::: "memory")
#define CP_WAIT0()  asm volatile("cp.async.wait_group 0;" ::: "memory")

__device__ __forceinline__ void ldsm4(uint32_t& r0, uint32_t& r1, uint32_t& r2, uint32_t& r3,
                                      uint32_t a) {
    asm volatile("ldmatrix.sync.aligned.m8n8.x4.shared.b16 {%0,%1,%2,%3}, [%4];"
                 : "=r"(r0), "=r"(r1), "=r"(r2), "=r"(r3) : "r"(a));
}
__device__ __forceinline__ void ldsm4t(uint32_t& r0, uint32_t& r1, uint32_t& r2, uint32_t& r3,
                                       uint32_t a) {
    asm volatile("ldmatrix.sync.aligned.m8n8.x4.trans.shared.b16 {%0,%1,%2,%3}, [%4];"
                 : "=r"(r0), "=r"(r1), "=r"(r2), "=r"(r3) : "r"(a));
}
__device__ __forceinline__ void mma_bf16(float* c, const uint32_t* a, const uint32_t* b) {
    asm volatile("mma.sync.aligned.m16n8k16.row.col.f32.bf16.bf16.f32 "
                 "{%0,%1,%2,%3}, {%4,%5,%6,%7}, {%8,%9}, {%0,%1,%2,%3};"
                 : "+f"(c[0]), "+f"(c[1]), "+f"(c[2]), "+f"(c[3])
                 : "r"(a[0]), "r"(a[1]), "r"(a[2]), "r"(a[3]), "r"(b[0]), "r"(b[1]));
}
__device__ __forceinline__ void mma_f16(float* c, const uint32_t* a, uint32_t b0, uint32_t b1) {
    asm volatile("mma.sync.aligned.m16n8k16.row.col.f32.f16.f16.f32 "
                 "{%0,%1,%2,%3}, {%4,%5,%6,%7}, {%8,%9}, {%0,%1,%2,%3};"
                 : "+f"(c[0]), "+f"(c[1]), "+f"(c[2]), "+f"(c[3])
                 : "r"(a[0]), "r"(a[1]), "r"(a[2]), "r"(a[3]), "r"(b0), "r"(b1));
}
__device__ __forceinline__ float ex2f(float x) {
    float y; asm("ex2.approx.ftz.f32 %0, %1;" : "=f"(y) : "f"(x)); return y;
}

// 128B-row tile swizzle (GEMM BK=64: 64 bf16/row, 8 chunks of 16B)
__device__ __forceinline__ uint32_t swz128(int row, int chunk) {
    return (uint32_t)(row * 128 + ((chunk ^ (row & 7)) << 4));
}
// 256B-row tile swizzle (attention, 128 b16/row, 16 chunks of 16B)
__device__ __forceinline__ uint32_t swz256(int row, int chunk) {
    return (uint32_t)(row * 256 + ((chunk ^ (row & 7)) << 4));
}

// =====================================================================
// fp32 -> bf16 hi/lo split
// =====================================================================
__global__ void conv_split(const float* __restrict__ x,
                           __nv_bfloat16* __restrict__ hi,
                           __nv_bfloat16* __restrict__ lo, int n4)
{
    const int i = blockIdx.x * blockDim.x + threadIdx.x;
    if (i >= n4) return;
    const float4 v = ((const float4*)x)[i];
    __nv_bfloat16 h0 = __float2bfloat16_rn(v.x);
    __nv_bfloat16 h1 = __float2bfloat16_rn(v.y);
    __nv_bfloat16 h2 = __float2bfloat16_rn(v.z);
    __nv_bfloat16 h3 = __float2bfloat16_rn(v.w);
    __nv_bfloat16 l0 = __float2bfloat16_rn(v.x - __bfloat162float(h0));
    __nv_bfloat16 l1 = __float2bfloat16_rn(v.y - __bfloat162float(h1));
    __nv_bfloat16 l2 = __float2bfloat16_rn(v.z - __bfloat162float(h2));
    __nv_bfloat16 l3 = __float2bfloat16_rn(v.w - __bfloat162float(h3));
    __nv_bfloat162* H = (__nv_bfloat162*)(hi + (size_t)i * 4);
    __nv_bfloat162* L = (__nv_bfloat162*)(lo + (size_t)i * 4);
    H[0] = __nv_bfloat162(h0, h1); H[1] = __nv_bfloat162(h2, h3);
    L[0] = __nv_bfloat162(l0, l1); L[1] = __nv_bfloat162(l2, l3);
}

// =====================================================================
// HMMA bf16x3 GEMM  C[M,Nt] = A[M,KT]*B[Nt,KT]^T (+bias)
// 128x128 CTA tile, 8 warps (4M x 2N), warp tile 32x64, BK=64.
// 3-stage cp.async pipeline (96KB dynamic smem), logical K = 3*KT.
// =====================================================================
template<int BIAS>
__global__ void __launch_bounds__(256, 2) tc_gemm(const __nv_bfloat16* __restrict__ ah,
                                                  const __nv_bfloat16* __restrict__ al,
                                                  const __nv_bfloat16* __restrict__ bh,
                                                  const __nv_bfloat16* __restrict__ bl,
                                                  const float* __restrict__ bias,
                                                  float* __restrict__ C, int Nt)
{
    extern __shared__ __align__(1024) char smem[];   // 3 stages x (A 16K + B 16K)
    const uint32_t smem_u = smem_to_u32(smem);

    const int tid  = threadIdx.x;
    const int wid  = tid >> 5;
    const int lane = tid & 31;
    const int wm   = wid & 3;          // warp M index (0..3)
    const int wn   = wid >> 2;         // warp N index (0..1)
    const int n0   = blockIdx.x * 128;
    const int m0   = blockIdx.y * 128;

    // loader mapping: chunk id q ∈ [0,1024): row = q>>3, chunk = q&7
    int lrow[4]; uint32_t soff[4];
#pragma unroll
    for (int i = 0; i < 4; i++) {
        const int q = tid + 256 * i;
        lrow[i] = q >> 3;
        soff[i] = swz128(q >> 3, q & 7);
    }
    const int lchunk = tid & 7;

    // ldmatrix lane address components
    const int g = lane >> 3, j = lane & 7;
    uint32_t a_off[2][4];   // [mt][kc]
#pragma unroll
    for (int mt = 0; mt < 2; mt++)
#pragma unroll
        for (int kc = 0; kc < 4; kc++) {
            const int row = wm * 32 + mt * 16 + (g & 1) * 8 + j;
            a_off[mt][kc] = swz128(row, kc * 2 + (g >> 1));
        }
    uint32_t b_off[4][4];   // [nt16][kc]
#pragma unroll
    for (int nt = 0; nt < 4; nt++)
#pragma unroll
        for (int kc = 0; kc < 4; kc++) {
            const int row = wn * 64 + nt * 16 + (g >> 1) * 8 + j;
            b_off[nt][kc] = swz128(row, kc * 2 + (g & 1));
        }

    float acc[2][8][4];
#pragma unroll
    for (int mi = 0; mi < 2; mi++)
#pragma unroll
        for (int ni = 0; ni < 8; ni++)
#pragma unroll
            for (int k = 0; k < 4; k++) acc[mi][ni][k] = 0.f;

    auto load_stage = [&](int s, int buf) {
        const int pass = s / PASSLEN64;
        const int k0   = (s % PASSLEN64) * 64;
        const __nv_bfloat16* Ap = (pass < 2) ? ah : al;
        const __nv_bfloat16* Bp = (pass == 1) ? bl : bh;
        const uint32_t Au = smem_u + buf * 32768;
        const uint32_t Bu = Au + 16384;
#pragma unroll
        for (int i = 0; i < 4; i++) {
            cpasync16(Au + soff[i], Ap + (size_t)(m0 + lrow[i]) * KT + k0 + lchunk * 8);
            cpasync16(Bu + soff[i], Bp + (size_t)(n0 + lrow[i]) * KT + k0 + lchunk * 8);
        }
    };

    load_stage(0, 0); CP_COMMIT();
    load_stage(1, 1); CP_COMMIT();

#pragma unroll 1
    for (int s = 0; s < KSTEPS64; s++) {
        CP_WAIT1();
        __syncthreads();
        const int buf = s % 3;
        if (s + 2 < KSTEPS64) load_stage(s + 2, (s + 2) % 3);
        CP_COMMIT();

        const uint32_t Au = smem_u + buf * 32768;
        const uint32_t Bu = Au + 16384;
#pragma unroll
        for (int kc = 0; kc < 4; kc++) {
            uint32_t a[2][4];
            ldsm4(a[0][0], a[0][1], a[0][2], a[0][3], Au + a_off[0][kc]);
            ldsm4(a[1][0], a[1][1], a[1][2], a[1][3], Au + a_off[1][kc]);
            uint32_t b[8][2];
#pragma unroll
            for (int nt = 0; nt < 4; nt++)
                ldsm4(b[2 * nt][0], b[2 * nt][1], b[2 * nt + 1][0], b[2 * nt + 1][1],
                      Bu + b_off[nt][kc]);
#pragma unroll
            for (int mi = 0; mi < 2; mi++)
#pragma unroll
                for (int ni = 0; ni < 8; ni++)
                    mma_bf16(acc[mi][ni], a[mi], b[ni]);
        }
    }

    const int r0 = m0 + wm * 32 + (lane >> 2);
    const int c0 = n0 + wn * 64 + (lane & 3) * 2;
#pragma unroll
    for (int mi = 0; mi < 2; mi++)
#pragma unroll
        for (int ni = 0; ni < 8; ni++) {
            const int row = r0 + mi * 16;
            const int col = c0 + ni * 8;
            float b0 = 0.f, b1 = 0.f;
            if (BIAS) { b0 = bias[col]; b1 = bias[col + 1]; }
            *(float2*)&C[(size_t)row * Nt + col] =
                make_float2(acc[mi][ni][0] + b0, acc[mi][ni][1] + b1);
            *(float2*)&C[(size_t)(row + 8) * Nt + col] =
                make_float2(acc[mi][ni][2] + b0, acc[mi][ni][3] + b1);
        }
}

// =====================================================================
// RoPE: q -> bf16 hi/lo scratch; k -> fp32 cache + bf16 hi/lo;
//       v -> fp32 cache + f16 hi/lo
// =====================================================================
__global__ void rope_scatter(const int* __restrict__ positions,
                             const int* __restrict__ slot_mapping,
                             float* __restrict__ cache_out)
{
    const int idx = blockIdx.x * blockDim.x + threadIdx.x;
    const int total = TT * 36 * 64;
    if (idx >= total) return;
    const int i  = idx & 63;
    const int hh = (idx >> 6) % 36;
    const int t  = idx / (36 * 64);

    if (hh < 32) {
        const float pos = (float)positions[t];
        const float inv = exp2f(-(float)i * (13.287712379549449f / 64.0f));
        const float ang = pos * inv;
        float s, c;
        sincosf(ang, &s, &c);
        if (hh < 28) {
            const float* p = g_qkv + (size_t)t * QKVO + hh * DH;
            const float x1 = p[i], x2 = p[i + 64];
            const float r1 = x1 * c - x2 * s;
            const float r2 = x2 * c + x1 * s;
            const size_t o = (size_t)t * HH + hh * DH;
            __nv_bfloat16 h1 = __float2bfloat16_rn(r1);
            __nv_bfloat16 h2 = __float2bfloat16_rn(r2);
            g_qh[o + i]      = h1;
            g_qh[o + i + 64] = h2;
            g_ql[o + i]      = __float2bfloat16_rn(r1 - __bfloat162float(h1));
            g_ql[o + i + 64] = __float2bfloat16_rn(r2 - __bfloat162float(h2));
        } else {
            const int kvh = hh - 28;
            const float* p = g_qkv + (size_t)t * QKVO + NHEADS * DH + kvh * DH;
            const float x1 = p[i], x2 = p[i + 64];
            const float r1 = x1 * c - x2 * s;
            const float r2 = x2 * c + x1 * s;
            const size_t o = (size_t)t * KROW + kvh * DH;
            __nv_bfloat16 h1 = __float2bfloat16_rn(r1);
            __nv_bfloat16 h2 = __float2bfloat16_rn(r2);
            g_kh[o + i]      = h1;
            g_kh[o + i + 64] = h2;
            g_kl[o + i]      = __float2bfloat16_rn(r1 - __bfloat162float(h1));
            g_kl[o + i + 64] = __float2bfloat16_rn(r2 - __bfloat162float(h2));
            const int slot = slot_mapping[t];
            float* dst = cache_out + (size_t)slot * KROW + kvh * DH;
            dst[i]      = r1;
            dst[i + 64] = r2;
        }
    } else {
        const int kvh = hh - 32;
        const float* p = g_qkv + (size_t)t * QKVO + (NHEADS + NKVH) * DH + kvh * DH;
        const float v1 = p[i], v2 = p[i + 64];
        const size_t o = (size_t)t * KROW + kvh * DH;
        __half h1 = __float2half_rn(v1);
        __half h2 = __float2half_rn(v2);
        g_vh[o + i]      = h1;
        g_vh[o + i + 64] = h2;
        g_vl[o + i]      = __float2half_rn(v1 - __half2float(h1));
        g_vl[o + i + 64] = __float2half_rn(v2 - __half2float(h2));
        const int slot = slot_mapping[t];
        float* dst = cache_out + (size_t)CACHE_HALF + (size_t)slot * KROW + kvh * DH;
        dst[i]      = v1;
        dst[i + 64] = v2;
    }
}

// =====================================================================
// Tensor-core flash attention (causal, GQA) — unchanged from round 7
// =====================================================================
__global__ void __launch_bounds__(128) attn_fwd_tc(
    __nv_bfloat16* __restrict__ ch_g, __nv_bfloat16* __restrict__ cl_g)
{
    extern __shared__ __align__(1024) char smem[];
    const uint32_t su = smem_to_u32(smem);
    const uint32_t Qh = su, Ql = su + 16384, Kh = su + 32768, Kl = su + 49152,
                   Vh = su + 65536, Vl = su + 81920;

    const int qt  = (gridDim.x - 1) - blockIdx.x;
    const int h   = blockIdx.y, b = blockIdx.z;
    const int kvh = h / GROUP;
    const int tid = threadIdx.x, wid = tid >> 5, lane = tid & 31;
    const int g   = lane >> 3, jj = lane & 7;

    const int lrow = tid & 63, lc0 = (tid >> 6) * 8;

    {
        const size_t t = (size_t)(b * SEQ + qt * 64 + lrow);
        const __nv_bfloat16* gh = g_qh + t * HH + h * DH + lc0 * 8;
        const __nv_bfloat16* gl = g_ql + t * HH + h * DH + lc0 * 8;
#pragma unroll
        for (int i = 0; i < 8; i++) {
            cpasync16(Qh + swz256(lrow, lc0 + i), gh + i * 8);
            cpasync16(Ql + swz256(lrow, lc0 + i), gl + i * 8);
        }
    }
    CP_COMMIT();

    const int arow = wid * 16 + (g & 1) * 8 + jj;
    const int acb  = g >> 1;
    const int brow = (g >> 1) * 8 + jj;
    const int bcb  = g & 1;
    const int vrow = (g & 1) * 8 + jj;
    const int vcb  = g >> 1;

    float O[16][4];
#pragma unroll
    for (int nt = 0; nt < 16; nt++)
#pragma unroll
        for (int k = 0; k < 4; k++) O[nt][k] = 0.f;
    float m0 = -1e30f, m1 = -1e30f, l0 = 0.f, l1 = 0.f;
    const float K1 = SCALE * 1.4426950408889634f;

#pragma unroll 1
    for (int j = 0; j <= qt; j++) {
        {
            const size_t t = (size_t)(b * SEQ + j * 64 + lrow);
            const __nv_bfloat16* kh = g_kh + t * KROW + kvh * DH + lc0 * 8;
            const __nv_bfloat16* kl = g_kl + t * KROW + kvh * DH + lc0 * 8;
            const __half* vh = g_vh + t * KROW + kvh * DH + lc0 * 8;
            const __half* vl = g_vl + t * KROW + kvh * DH + lc0 * 8;
#pragma unroll
            for (int i = 0; i < 8; i++) {
                const uint32_t so = swz256(lrow, lc0 + i);
                cpasync16(Kh + so, kh + i * 8);
                cpasync16(Kl + so, kl + i * 8);
                cpasync16(Vh + so, vh + i * 8);
                cpasync16(Vl + so, vl + i * 8);
            }
        }
        CP_COMMIT(); CP_WAIT0();
        __syncthreads();

        float sa[8][4];
#pragma unroll
        for (int nt = 0; nt < 8; nt++)
#pragma unroll
            for (int k = 0; k < 4; k++) sa[nt][k] = 0.f;

#pragma unroll
        for (int ds = 0; ds < 8; ds++) {
            uint32_t qhf[4], qlf[4];
            ldsm4(qhf[0], qhf[1], qhf[2], qhf[3], Qh + swz256(arow, ds * 2 + acb));
            ldsm4(qlf[0], qlf[1], qlf[2], qlf[3], Ql + swz256(arow, ds * 2 + acb));
#pragma unroll
            for (int p = 0; p < 4; p++) {
                uint32_t h0, h1, h2, h3, e0, e1, e2, e3;
                const uint32_t ko = swz256(p * 16 + brow, ds * 2 + bcb);
                ldsm4(h0, h1, h2, h3, Kh + ko);
                ldsm4(e0, e1, e2, e3, Kl + ko);
                {
                    uint32_t bb[2] = {h0, h1};
                    mma_bf16(sa[2 * p], qhf, bb);
                    uint32_t ll[2] = {e0, e1};
                    mma_bf16(sa[2 * p], qhf, ll);
                    mma_bf16(sa[2 * p], qlf, bb);
                }
                {
                    uint32_t bb[2] = {h2, h3};
                    mma_bf16(sa[2 * p + 1], qhf, bb);
                    uint32_t ll[2] = {e2, e3};
                    mma_bf16(sa[2 * p + 1], qhf, ll);
                    mma_bf16(sa[2 * p + 1], qlf, bb);
                }
            }
        }

        const int row0 = wid * 16 + (lane >> 2);
#pragma unroll
        for (int nt = 0; nt < 8; nt++)
#pragma unroll
            for (int k = 0; k < 4; k++) sa[nt][k] *= K1;
        if (j == qt) {
#pragma unroll
            for (int nt = 0; nt < 8; nt++) {
                const int cb = nt * 8 + 2 * (lane & 3);
                if (cb > row0)         sa[nt][0] = -1e30f;
                if (cb + 1 > row0)     sa[nt][1] = -1e30f;
                if (cb > row0 + 8)     sa[nt][2] = -1e30f;
                if (cb + 1 > row0 + 8) sa[nt][3] = -1e30f;
            }
        }

        float mt0 = -1e30f, mt1 = -1e30f;
#pragma unroll
        for (int nt = 0; nt < 8; nt++) {
            mt0 = fmaxf(mt0, fmaxf(sa[nt][0], sa[nt][1]));
            mt1 = fmaxf(mt1, fmaxf(sa[nt][2], sa[nt][3]));
        }
        mt0 = fmaxf(mt0, __shfl_xor_sync(0xffffffffu, mt0, 1));
        mt0 = fmaxf(mt0, __shfl_xor_sync(0xffffffffu, mt0, 2));
        mt1 = fmaxf(mt1, __shfl_xor_sync(0xffffffffu, mt1, 1));
        mt1 = fmaxf(mt1, __shfl_xor_sync(0xffffffffu, mt1, 2));
        const float mn0 = fmaxf(m0, mt0), mn1 = fmaxf(m1, mt1);
        const float cr0 = ex2f(m0 - mn0), cr1 = ex2f(m1 - mn1);
        m0 = mn0; m1 = mn1;

        uint32_t p2[2][8];
        float s0 = 0.f, s1 = 0.f;
#pragma unroll
        for (int nt = 0; nt < 8; nt++) {
            const float e0 = ex2f(sa[nt][0] - m0);
            const float e1 = ex2f(sa[nt][1] - m0);
            const float e2 = ex2f(sa[nt][2] - m1);
            const float e3 = ex2f(sa[nt][3] - m1);
            s0 += e0 + e1; s1 += e2 + e3;
            p2[0][nt] = __half2_raw(__floats2half2_rn(e0, e1)).x |
                        ((uint32_t)__half2_raw(__floats2half2_rn(e0, e1)).y << 16);
            p2[1][nt] = __half2_raw(__floats2half2_rn(e2, e3)).x |
                        ((uint32_t)__half2_raw(__floats2half2_rn(e2, e3)).y << 16);
        }
        s0 += __shfl_xor_sync(0xffffffffu, s0, 1);
        s0 += __shfl_xor_sync(0xffffffffu, s0, 2);
        s1 += __shfl_xor_sync(0xffffffffu, s1, 1);
        s1 += __shfl_xor_sync(0xffffffffu, s1, 2);
        l0 = l0 * cr0 + s0;
        l1 = l1 * cr1 + s1;
#pragma unroll
        for (int nt = 0; nt < 16; nt++) {
            O[nt][0] *= cr0; O[nt][1] *= cr0;
            O[nt][2] *= cr1; O[nt][3] *= cr1;
        }

#pragma unroll
        for (int ks = 0; ks < 4; ks++) {
            uint32_t af[4] = {p2[0][2 * ks], p2[1][2 * ks],
                              p2[0][2 * ks + 1], p2[1][2 * ks + 1]};
#pragma unroll
            for (int p = 0; p < 8; p++) {
                const uint32_t vo = swz256(ks * 16 + vrow, p * 2 + vcb);
                uint32_t v0, v1, v2, v3;
                ldsm4t(v0, v1, v2, v3, Vh + vo);
                mma_f16(O[2 * p],     af, v0, v1);
                mma_f16(O[2 * p + 1], af, v2, v3);
                ldsm4t(v0, v1, v2, v3, Vl + vo);
                mma_f16(O[2 * p],     af, v0, v1);
                mma_f16(O[2 * p + 1], af, v2, v3);
            }
        }
        __syncthreads();
    }

    const float il0 = 1.f / l0, il1 = 1.f / l1;
    const int row0 = wid * 16 + (lane >> 2);
    const size_t t0 = (size_t)(b * SEQ + qt * 64 + row0);
    const size_t t1 = t0 + 8;
#pragma unroll
    for (int nt = 0; nt < 16; nt++) {
        const int d = h * DH + nt * 8 + 2 * (lane & 3);
        {
            const float x0 = O[nt][0] * il0, x1 = O[nt][1] * il0;
            __nv_bfloat16 h0 = __float2bfloat16_rn(x0);
            __nv_bfloat16 h1 = __float2bfloat16_rn(x1);
            *(__nv_bfloat162*)&ch_g[t0 * HH + d] = __nv_bfloat162(h0, h1);
            *(__nv_bfloat162*)&cl_g[t0 * HH + d] = __nv_bfloat162(
                __float2bfloat16_rn(x0 - __bfloat162float(h0)),
                __float2bfloat16_rn(x1 - __bfloat162float(h1)));
        }
        {
            const float x0 = O[nt][2] * il1, x1 = O[nt][3] * il1;
            __nv_bfloat16 h0 = __float2bfloat16_rn(x0);
            __nv_bfloat16 h1 = __float2bfloat16_rn(x1);
            *(__nv_bfloat162*)&ch_g[t1 * HH + d] = __nv_bfloat162(h0, h1);
            *(__nv_bfloat162*)&cl_g[t1 * HH + d] = __nv_bfloat162(
                __float2bfloat16_rn(x0 - __bfloat162float(h0)),
                __float2bfloat16_rn(x1 - __bfloat162float(h1)));
        }
    }
}

// =====================================================================
// launch
// =====================================================================
extern "C" void kernel_launch(void* const* d_in, const int* in_sizes, int n_in,
                              void* d_out, int out_size)
{
    const float* hs = nullptr;
    const float* wqkv = nullptr;
    const float* bqkv = nullptr;
    const float* wo = nullptr;
    const float* kvc = nullptr;
    const int* positions = nullptr;
    const int* slot_mapping = nullptr;

    for (int i = 0; i < n_in; i++) {
        switch (in_sizes[i]) {
            case 14680064: hs   = (const float*)d_in[i]; break;
            case 16515072: wqkv = (const float*)d_in[i]; break;
            case 4608:     bqkv = (const float*)d_in[i]; break;
            case 12845056: wo   = (const float*)d_in[i]; break;
            case 8388608:  kvc  = (const float*)d_in[i]; break;
            case 4096:
                if (!positions)         positions    = (const int*)d_in[i];
                else if (!slot_mapping) slot_mapping = (const int*)d_in[i];
                break;
            default: break;
        }
    }

    float* out       = (float*)d_out;
    float* cache_out = out + OUT_ELEMS;

    float* qkv_ptr;
    __nv_bfloat16 *ah, *al, *wqh, *wql, *woh, *wol, *ch, *cl;
    cudaGetSymbolAddress((void**)&qkv_ptr, g_qkv);
    cudaGetSymbolAddress((void**)&ah, g_ah);
    cudaGetSymbolAddress((void**)&al, g_al);
    cudaGetSymbolAddress((void**)&wqh, g_wqh);
    cudaGetSymbolAddress((void**)&wql, g_wql);
    cudaGetSymbolAddress((void**)&woh, g_woh);
    cudaGetSymbolAddress((void**)&wol, g_wol);
    cudaGetSymbolAddress((void**)&ch, g_ch);
    cudaGetSymbolAddress((void**)&cl, g_cl);

    const int gemm_smem = 3 * 32768;   // 96KB
    cudaFuncSetAttribute(tc_gemm<1>, cudaFuncAttributeMaxDynamicSharedMemorySize, gemm_smem);
    cudaFuncSetAttribute(tc_gemm<0>, cudaFuncAttributeMaxDynamicSharedMemorySize, gemm_smem);
    const int attn_smem = 6 * 16384;   // 96KB
    cudaFuncSetAttribute(attn_fwd_tc, cudaFuncAttributeMaxDynamicSharedMemorySize, attn_smem);

    // 0) bf16 hi/lo splits of activations + weights
    conv_split<<<(TT * HH / 4 + 255) / 256, 256>>>(hs, ah, al, TT * HH / 4);
    conv_split<<<(QKVO * HH / 4 + 255) / 256, 256>>>(wqkv, wqh, wql, QKVO * HH / 4);
    conv_split<<<(HH * HH / 4 + 255) / 256, 256>>>(wo, woh, wol, HH * HH / 4);

    // 1) QKV projection (HMMA bf16x3, BK=64)
    tc_gemm<1><<<dim3(QKVO / 128, TT / 128), 256, gemm_smem>>>(ah, al, wqh, wql, bqkv,
                                                               qkv_ptr, QKVO);

    // 2) copy input cache into output cache region
    cudaMemcpyAsync(cache_out, kvc, (size_t)2 * CACHE_HALF * sizeof(float),
                    cudaMemcpyDeviceToDevice);

    // 3) RoPE + scatter + bf16/f16 operand prep
    {
        const int total = TT * 36 * 64;
        rope_scatter<<<(total + 255) / 256, 256>>>(positions, slot_mapping, cache_out);
    }

    // 4) tensor-core causal GQA flash attention -> ctx bf16 hi/lo
    attn_fwd_tc<<<dim3(SEQ / 64, NHEADS, NBATCH), 128, attn_smem>>>(ch, cl);

    // 5) output projection (HMMA bf16x3, BK=64)
    tc_gemm<0><<<dim3(HH / 128, TT / 128), 256, gemm_smem>>>(ch, cl, woh, wol, nullptr,
                                                             out, HH);

    (void)out_size;
}

// round 14
// speedup vs baseline: 7.6170x; 2.2684x over previous
#include <cuda_runtime.h>
#include <cuda_bf16.h>
#include <cuda_fp16.h>
#include <math.h>
#include <stdint.h>

// ---------------- problem constants ----------------
#define TT      4096            // B*S tokens
#define HH      3584            // hidden
#define NHEADS  28
#define NKVH    4
#define GROUP   7
#define DH      128
#define QKVO    4608            // (28 + 2*4) * 128
#define SEQ     1024
#define NBATCH  4
#define KROW    512             // NKV*D, cache row per slot
#define CACHE_HALF 4194304      // NB*BS*NKV*D
#define OUT_ELEMS  14680064     // TT*HH
#define SCALE   0.088388347648318447f   // 1/sqrt(128)
#define KT      3584            // GEMM K (both projections)
#define PASSLEN64 (KT / 64)     // 56 k-stages of 64 per pass

// ---------------- scratch (device globals; no allocation) ----------------
__device__ float  g_qkv[(size_t)TT * QKVO];
__device__ __half g_af[(size_t)TT * HH];        // hidden f16
__device__ __half g_wqh[(size_t)QKVO * HH];     // w_qkv f16 hi
__device__ __half g_wql[(size_t)QKVO * HH];     // w_qkv f16 lo (used for KV rows)
__device__ __half g_wof[(size_t)HH * HH];       // w_o f16
__device__ __half g_cf[(size_t)TT * HH];        // ctx f16 (written by attention)
__device__ __half g_qf[(size_t)TT * HH];        // rope'd Q f16
__device__ __half g_kf[(size_t)TT * KROW];      // rope'd K f16
__device__ __half g_vf[(size_t)TT * KROW];      // V f16

// ---------------- PTX helpers (baseline features only) ----------------
__device__ __forceinline__ uint32_t smem_to_u32(const void* p) {
    uint32_t a;
    asm("{ .reg .u64 t; cvta.to.shared.u64 t, %1; cvt.u32.u64 %0, t; }" : "=r"(a) : "l"(p));
    return a;
}
__device__ __forceinline__ void cpasync16(uint32_t dst, const void* src) {
    asm volatile("cp.async.cg.shared.global [%0], [%1], 16;" :: "r"(dst), "l"(src));
}
#define CP_COMMIT() asm volatile("cp.async.commit_group;" ::: "memory")
#define CP_WAIT1()  asm volatile("cp.async.wait_group 1;" ::: "memory")
#define CP_WAIT0()  asm volatile("cp.async.wait_group 0;" ::: "memory")

__device__ __forceinline__ void ldsm4(uint32_t& r0, uint32_t& r1, uint32_t& r2, uint32_t& r3,
                                      uint32_t a) {
    asm volatile("ldmatrix.sync.aligned.m8n8.x4.shared.b16 {%0,%1,%2,%3}, [%4];"
                 : "=r"(r0), "=r"(r1), "=r"(r2), "=r"(r3) : "r"(a));
}
__device__ __forceinline__ void ldsm4t(uint32_t& r0, uint32_t& r1, uint32_t& r2, uint32_t& r3,
                                       uint32_t a) {
    asm volatile("ldmatrix.sync.aligned.m8n8.x4.trans.shared.b16 {%0,%1,%2,%3}, [%4];"
                 : "=r"(r0), "=r"(r1), "=r"(r2), "=r"(r3) : "r"(a));
}
__device__ __forceinline__ void mma_f16(float* c, const uint32_t* a, uint32_t b0, uint32_t b1) {
    asm volatile("mma.sync.aligned.m16n8k16.row.col.f32.f16.f16.f32 "
                 "{%0,%1,%2,%3}, {%4,%5,%6,%7}, {%8,%9}, {%0,%1,%2,%3};"
                 : "+f"(c[0]), "+f"(c[1]), "+f"(c[2]), "+f"(c[3])
                 : "r"(a[0]), "r"(a[1]), "r"(a[2]), "r"(a[3]), "r"(b0), "r"(b1));
}
__device__ __forceinline__ float ex2f(float x) {
    float y; asm("ex2.approx.ftz.f32 %0, %1;" : "=f"(y) : "f"(x)); return y;
}

// 128B-row tile swizzle (GEMM BK=64: 64 f16/row, 8 chunks of 16B)
__device__ __forceinline__ uint32_t swz128(int row, int chunk) {
    return (uint32_t)(row * 128 + ((chunk ^ (row & 7)) << 4));
}
// 256B-row tile swizzle (attention, 128 f16/row, 16 chunks of 16B)
__device__ __forceinline__ uint32_t swz256(int row, int chunk) {
    return (uint32_t)(row * 256 + ((chunk ^ (row & 7)) << 4));
}

// =====================================================================
// fp32 -> f16 single convert
// =====================================================================
__global__ void conv_f16(const float* __restrict__ x, __half* __restrict__ o, int n4)
{
    const int i = blockIdx.x * blockDim.x + threadIdx.x;
    if (i >= n4) return;
    const float4 v = ((const float4*)x)[i];
    __half2* O = (__half2*)(o + (size_t)i * 4);
    O[0] = __floats2half2_rn(v.x, v.y);
    O[1] = __floats2half2_rn(v.z, v.w);
}

// fp32 -> f16 hi + f16 lo split
__global__ void conv_split_f16(const float* __restrict__ x,
                               __half* __restrict__ hi, __half* __restrict__ lo, int n4)
{
    const int i = blockIdx.x * blockDim.x + threadIdx.x;
    if (i >= n4) return;
    const float4 v = ((const float4*)x)[i];
    __half h0 = __float2half_rn(v.x), h1 = __float2half_rn(v.y);
    __half h2 = __float2half_rn(v.z), h3 = __float2half_rn(v.w);
    __half2* H = (__half2*)(hi + (size_t)i * 4);
    __half2* L = (__half2*)(lo + (size_t)i * 4);
    H[0] = __half2(h0, h1); H[1] = __half2(h2, h3);
    L[0] = __floats2half2_rn(v.x - __half2float(h0), v.y - __half2float(h1));
    L[1] = __floats2half2_rn(v.z - __half2float(h2), v.w - __half2float(h3));
}

// =====================================================================
// HMMA f16 GEMM  C[M,*] = A[M,KT]*B[*,KT]^T (+bias)
// 128x128 CTA tile, 8 warps (4M x 2N), warp tile 32x64, BK=64.
// 3-stage cp.async pipeline (96KB dynamic smem).
// NPASS=1: A*Bh.  NPASS=2: A*Bh + A*Bl (B error-compensated).
// C/bias/B pointers are pre-offset by the caller for column sub-ranges.
// =====================================================================
template<int BIAS, int NPASS>
__global__ void __launch_bounds__(256, 2) tc_gemm(const __half* __restrict__ A,
                                                  const __half* __restrict__ Bh,
                                                  const __half* __restrict__ Bl,
                                                  const float* __restrict__ bias,
                                                  float* __restrict__ C, int Nt)
{
    extern __shared__ __align__(1024) char smem[];   // 3 stages x (A 16K + B 16K)
    const uint32_t smem_u = smem_to_u32(smem);
    const int KSTEPS = NPASS * PASSLEN64;

    const int tid  = threadIdx.x;
    const int wid  = tid >> 5;
    const int lane = tid & 31;
    const int wm   = wid & 3;
    const int wn   = wid >> 2;
    const int n0   = blockIdx.x * 128;
    const int m0   = blockIdx.y * 128;

    int lrow[4]; uint32_t soff[4];
#pragma unroll
    for (int i = 0; i < 4; i++) {
        const int q = tid + 256 * i;
        lrow[i] = q >> 3;
        soff[i] = swz128(q >> 3, q & 7);
    }
    const int lchunk = tid & 7;

    const int g = lane >> 3, j = lane & 7;
    uint32_t a_off[2][4];
#pragma unroll
    for (int mt = 0; mt < 2; mt++)
#pragma unroll
        for (int kc = 0; kc < 4; kc++) {
            const int row = wm * 32 + mt * 16 + (g & 1) * 8 + j;
            a_off[mt][kc] = swz128(row, kc * 2 + (g >> 1));
        }
    uint32_t b_off[4][4];
#pragma unroll
    for (int nt = 0; nt < 4; nt++)
#pragma unroll
        for (int kc = 0; kc < 4; kc++) {
            const int row = wn * 64 + nt * 16 + (g >> 1) * 8 + j;
            b_off[nt][kc] = swz128(row, kc * 2 + (g & 1));
        }

    float acc[2][8][4];
#pragma unroll
    for (int mi = 0; mi < 2; mi++)
#pragma unroll
        for (int ni = 0; ni < 8; ni++)
#pragma unroll
            for (int k = 0; k < 4; k++) acc[mi][ni][k] = 0.f;

    auto load_stage = [&](int s, int buf) {
        const int pass = s / PASSLEN64;
        const int k0   = (s % PASSLEN64) * 64;
        const __half* Bp = (NPASS == 2 && pass == 1) ? Bl : Bh;
        const uint32_t Au = smem_u + buf * 32768;
        const uint32_t Bu = Au + 16384;
#pragma unroll
        for (int i = 0; i < 4; i++) {
            cpasync16(Au + soff[i], A  + (size_t)(m0 + lrow[i]) * KT + k0 + lchunk * 8);
            cpasync16(Bu + soff[i], Bp + (size_t)(n0 + lrow[i]) * KT + k0 + lchunk * 8);
        }
    };

    load_stage(0, 0); CP_COMMIT();
    load_stage(1, 1); CP_COMMIT();

#pragma unroll 1
    for (int s = 0; s < KSTEPS; s++) {
        CP_WAIT1();
        __syncthreads();
        const int buf = s % 3;
        if (s + 2 < KSTEPS) load_stage(s + 2, (s + 2) % 3);
        CP_COMMIT();

        const uint32_t Au = smem_u + buf * 32768;
        const uint32_t Bu = Au + 16384;
#pragma unroll
        for (int kc = 0; kc < 4; kc++) {
            uint32_t a[2][4];
            ldsm4(a[0][0], a[0][1], a[0][2], a[0][3], Au + a_off[0][kc]);
            ldsm4(a[1][0], a[1][1], a[1][2], a[1][3], Au + a_off[1][kc]);
            uint32_t b[8][2];
#pragma unroll
            for (int nt = 0; nt < 4; nt++)
                ldsm4(b[2 * nt][0], b[2 * nt][1], b[2 * nt + 1][0], b[2 * nt + 1][1],
                      Bu + b_off[nt][kc]);
#pragma unroll
            for (int mi = 0; mi < 2; mi++)
#pragma unroll
                for (int ni = 0; ni < 8; ni++)
                    mma_f16(acc[mi][ni], a[mi], b[ni][0], b[ni][1]);
        }
    }

    const int r0 = m0 + wm * 32 + (lane >> 2);
    const int c0 = n0 + wn * 64 + (lane & 3) * 2;
#pragma unroll
    for (int mi = 0; mi < 2; mi++)
#pragma unroll
        for (int ni = 0; ni < 8; ni++) {
            const int row = r0 + mi * 16;
            const int col = c0 + ni * 8;
            float b0 = 0.f, b1 = 0.f;
            if (BIAS) { b0 = bias[col]; b1 = bias[col + 1]; }
            *(float2*)&C[(size_t)row * Nt + col] =
                make_float2(acc[mi][ni][0] + b0, acc[mi][ni][1] + b1);
            *(float2*)&C[(size_t)(row + 8) * Nt + col] =
                make_float2(acc[mi][ni][2] + b0, acc[mi][ni][3] + b1);
        }
}

// =====================================================================
// RoPE: q -> f16 scratch; k -> fp32 cache + f16; v -> fp32 cache + f16
// =====================================================================
__global__ void rope_scatter(const int* __restrict__ positions,
                             const int* __restrict__ slot_mapping,
                             float* __restrict__ cache_out)
{
    const int idx = blockIdx.x * blockDim.x + threadIdx.x;
    const int total = TT * 36 * 64;
    if (idx >= total) return;
    const int i  = idx & 63;
    const int hh = (idx >> 6) % 36;
    const int t  = idx / (36 * 64);

    if (hh < 32) {
        const float pos = (float)positions[t];
        const float inv = exp2f(-(float)i * (13.287712379549449f / 64.0f));
        const float ang = pos * inv;
        float s, c;
        sincosf(ang, &s, &c);
        if (hh < 28) {
            const float* p = g_qkv + (size_t)t * QKVO + hh * DH;
            const float x1 = p[i], x2 = p[i + 64];
            const size_t o = (size_t)t * HH + hh * DH;
            g_qf[o + i]      = __float2half_rn(x1 * c - x2 * s);
            g_qf[o + i + 64] = __float2half_rn(x2 * c + x1 * s);
        } else {
            const int kvh = hh - 28;
            const float* p = g_qkv + (size_t)t * QKVO + NHEADS * DH + kvh * DH;
            const float x1 = p[i], x2 = p[i + 64];
            const float r1 = x1 * c - x2 * s;
            const float r2 = x2 * c + x1 * s;
            const size_t o = (size_t)t * KROW + kvh * DH;
            g_kf[o + i]      = __float2half_rn(r1);
            g_kf[o + i + 64] = __float2half_rn(r2);
            const int slot = slot_mapping[t];
            float* dst = cache_out + (size_t)slot * KROW + kvh * DH;
            dst[i]      = r1;
            dst[i + 64] = r2;
        }
    } else {
        const int kvh = hh - 32;
        const float* p = g_qkv + (size_t)t * QKVO + (NHEADS + NKVH) * DH + kvh * DH;
        const float v1 = p[i], v2 = p[i + 64];
        const size_t o = (size_t)t * KROW + kvh * DH;
        g_vf[o + i]      = __float2half_rn(v1);
        g_vf[o + i + 64] = __float2half_rn(v2);
        const int slot = slot_mapping[t];
        float* dst = cache_out + (size_t)CACHE_HALF + (size_t)slot * KROW + kvh * DH;
        dst[i]      = v1;
        dst[i + 64] = v2;
    }
}

// =====================================================================
// Tensor-core flash attention (causal, GQA), all-f16 single-pass.
// CTA = 64 q rows x head x batch; 4 warps; 48KB smem (Q,K,V f16 tiles).
// Writes ctx as f16 for the O-projection.
// =====================================================================
__global__ void __launch_bounds__(128) attn_fwd_tc(__half* __restrict__ cf_g)
{
    extern __shared__ __align__(1024) char smem[];
    const uint32_t su = smem_to_u32(smem);
    const uint32_t Qf = su, Kf = su + 16384, Vf = su + 32768;

    const int qt  = (gridDim.x - 1) - blockIdx.x;    // big tiles first
    const int h   = blockIdx.y, b = blockIdx.z;
    const int kvh = h / GROUP;
    const int tid = threadIdx.x, wid = tid >> 5, lane = tid & 31;
    const int g   = lane >> 3, jj = lane & 7;

    const int lrow = tid & 63, lc0 = (tid >> 6) * 8;

    // ---- Q tile (f16), loaded once ----
    {
        const size_t t = (size_t)(b * SEQ + qt * 64 + lrow);
        const __half* gq = g_qf + t * HH + h * DH + lc0 * 8;
#pragma unroll
        for (int i = 0; i < 8; i++)
            cpasync16(Qf + swz256(lrow, lc0 + i), gq + i * 8);
    }
    CP_COMMIT();

    const int arow = wid * 16 + (g & 1) * 8 + jj;
    const int acb  = g >> 1;
    const int brow = (g >> 1) * 8 + jj;
    const int bcb  = g & 1;
    const int vrow = (g & 1) * 8 + jj;
    const int vcb  = g >> 1;

    float O[16][4];
#pragma unroll
    for (int nt = 0; nt < 16; nt++)
#pragma unroll
        for (int k = 0; k < 4; k++) O[nt][k] = 0.f;
    float m0 = -1e30f, m1 = -1e30f, l0 = 0.f, l1 = 0.f;
    const float K1 = SCALE * 1.4426950408889634f;

#pragma unroll 1
    for (int j = 0; j <= qt; j++) {
        {
            const size_t t = (size_t)(b * SEQ + j * 64 + lrow);
            const __half* kk = g_kf + t * KROW + kvh * DH + lc0 * 8;
            const __half* vv = g_vf + t * KROW + kvh * DH + lc0 * 8;
#pragma unroll
            for (int i = 0; i < 8; i++) {
                const uint32_t so = swz256(lrow, lc0 + i);
                cpasync16(Kf + so, kk + i * 8);
                cpasync16(Vf + so, vv + i * 8);
            }
        }
        CP_COMMIT(); CP_WAIT0();
        __syncthreads();

        // ---- QK^T (f16 single pass) ----
        float sa[8][4];
#pragma unroll
        for (int nt = 0; nt < 8; nt++)
#pragma unroll
            for (int k = 0; k < 4; k++) sa[nt][k] = 0.f;

#pragma unroll
        for (int ds = 0; ds < 8; ds++) {
            uint32_t qf[4];
            ldsm4(qf[0], qf[1], qf[2], qf[3], Qf + swz256(arow, ds * 2 + acb));
#pragma unroll
            for (int p = 0; p < 4; p++) {
                uint32_t k0, k1, k2, k3;
                ldsm4(k0, k1, k2, k3, Kf + swz256(p * 16 + brow, ds * 2 + bcb));
                mma_f16(sa[2 * p],     qf, k0, k1);
                mma_f16(sa[2 * p + 1], qf, k2, k3);
            }
        }

        const int row0 = wid * 16 + (lane >> 2);
#pragma unroll
        for (int nt = 0; nt < 8; nt++)
#pragma unroll
            for (int k = 0; k < 4; k++) sa[nt][k] *= K1;
        if (j == qt) {
#pragma unroll
            for (int nt = 0; nt < 8; nt++) {
                const int cb = nt * 8 + 2 * (lane & 3);
                if (cb > row0)         sa[nt][0] = -1e30f;
                if (cb + 1 > row0)     sa[nt][1] = -1e30f;
                if (cb > row0 + 8)     sa[nt][2] = -1e30f;
                if (cb + 1 > row0 + 8) sa[nt][3] = -1e30f;
            }
        }

        // ---- online softmax ----
        float mt0 = -1e30f, mt1 = -1e30f;
#pragma unroll
        for (int nt = 0; nt < 8; nt++) {
            mt0 = fmaxf(mt0, fmaxf(sa[nt][0], sa[nt][1]));
            mt1 = fmaxf(mt1, fmaxf(sa[nt][2], sa[nt][3]));
        }
        mt0 = fmaxf(mt0, __shfl_xor_sync(0xffffffffu, mt0, 1));
        mt0 = fmaxf(mt0, __shfl_xor_sync(0xffffffffu, mt0, 2));
        mt1 = fmaxf(mt1, __shfl_xor_sync(0xffffffffu, mt1, 1));
        mt1 = fmaxf(mt1, __shfl_xor_sync(0xffffffffu, mt1, 2));
        const float mn0 = fmaxf(m0, mt0), mn1 = fmaxf(m1, mt1);
        const float cr0 = ex2f(m0 - mn0), cr1 = ex2f(m1 - mn1);
        m0 = mn0; m1 = mn1;

        uint32_t p2[2][8];
        float s0 = 0.f, s1 = 0.f;
#pragma unroll
        for (int nt = 0; nt < 8; nt++) {
            const float e0 = ex2f(sa[nt][0] - m0);
            const float e1 = ex2f(sa[nt][1] - m0);
            const float e2 = ex2f(sa[nt][2] - m1);
            const float e3 = ex2f(sa[nt][3] - m1);
            s0 += e0 + e1; s1 += e2 + e3;
            __half2 ha = __floats2half2_rn(e0, e1);
            __half2 hb = __floats2half2_rn(e2, e3);
            p2[0][nt] = *(uint32_t*)&ha;
            p2[1][nt] = *(uint32_t*)&hb;
        }
        s0 += __shfl_xor_sync(0xffffffffu, s0, 1);
        s0 += __shfl_xor_sync(0xffffffffu, s0, 2);
        s1 += __shfl_xor_sync(0xffffffffu, s1, 1);
        s1 += __shfl_xor_sync(0xffffffffu, s1, 2);
        l0 = l0 * cr0 + s0;
        l1 = l1 * cr1 + s1;
#pragma unroll
        for (int nt = 0; nt < 16; nt++) {
            O[nt][0] *= cr0; O[nt][1] *= cr0;
            O[nt][2] *= cr1; O[nt][3] *= cr1;
        }

        // ---- P @ V (f16 single pass) ----
#pragma unroll
        for (int ks = 0; ks < 4; ks++) {
            uint32_t af[4] = {p2[0][2 * ks], p2[1][2 * ks],
                              p2[0][2 * ks + 1], p2[1][2 * ks + 1]};
#pragma unroll
            for (int p = 0; p < 8; p++) {
                uint32_t v0, v1, v2, v3;
                ldsm4t(v0, v1, v2, v3, Vf + swz256(ks * 16 + vrow, p * 2 + vcb));
                mma_f16(O[2 * p],     af, v0, v1);
                mma_f16(O[2 * p + 1], af, v2, v3);
            }
        }
        __syncthreads();
    }

    // ---- epilogue: normalize, store f16 ctx ----
    const float il0 = 1.f / l0, il1 = 1.f / l1;
    const int row0 = wid * 16 + (lane >> 2);
    const size_t t0 = (size_t)(b * SEQ + qt * 64 + row0);
    const size_t t1 = t0 + 8;
#pragma unroll
    for (int nt = 0; nt < 16; nt++) {
        const int d = h * DH + nt * 8 + 2 * (lane & 3);
        *(__half2*)&cf_g[t0 * HH + d] = __floats2half2_rn(O[nt][0] * il0, O[nt][1] * il0);
        *(__half2*)&cf_g[t1 * HH + d] = __floats2half2_rn(O[nt][2] * il1, O[nt][3] * il1);
    }
}

// =====================================================================
// launch
// =====================================================================
extern "C" void kernel_launch(void* const* d_in, const int* in_sizes, int n_in,
                              void* d_out, int out_size)
{
    const float* hs = nullptr;
    const float* wqkv = nullptr;
    const float* bqkv = nullptr;
    const float* wo = nullptr;
    const float* kvc = nullptr;
    const int* positions = nullptr;
    const int* slot_mapping = nullptr;

    for (int i = 0; i < n_in; i++) {
        switch (in_sizes[i]) {
            case 14680064: hs   = (const float*)d_in[i]; break;
            case 16515072: wqkv = (const float*)d_in[i]; break;
            case 4608:     bqkv = (const float*)d_in[i]; break;
            case 12845056: wo   = (const float*)d_in[i]; break;
            case 8388608:  kvc  = (const float*)d_in[i]; break;
            case 4096:
                if (!positions)         positions    = (const int*)d_in[i];
                else if (!slot_mapping) slot_mapping = (const int*)d_in[i];
                break;
            default: break;
        }
    }

    float* out       = (float*)d_out;
    float* cache_out = out + OUT_ELEMS;

    float* qkv_ptr;
    __half *af, *wqh, *wql, *wof, *cf;
    cudaGetSymbolAddress((void**)&qkv_ptr, g_qkv);
    cudaGetSymbolAddress((void**)&af, g_af);
    cudaGetSymbolAddress((void**)&wqh, g_wqh);
    cudaGetSymbolAddress((void**)&wql, g_wql);
    cudaGetSymbolAddress((void**)&wof, g_wof);
    cudaGetSymbolAddress((void**)&cf, g_cf);

    const int gemm_smem = 3 * 32768;   // 96KB
    cudaFuncSetAttribute(tc_gemm<1,1>, cudaFuncAttributeMaxDynamicSharedMemorySize, gemm_smem);
    cudaFuncSetAttribute(tc_gemm<1,2>, cudaFuncAttributeMaxDynamicSharedMemorySize, gemm_smem);
    cudaFuncSetAttribute(tc_gemm<0,1>, cudaFuncAttributeMaxDynamicSharedMemorySize, gemm_smem);
    const int attn_smem = 3 * 16384;   // 48KB
    cudaFuncSetAttribute(attn_fwd_tc, cudaFuncAttributeMaxDynamicSharedMemorySize, attn_smem);

    // 0) f16 conversions
    conv_f16<<<(TT * HH / 4 + 255) / 256, 256>>>(hs, af, TT * HH / 4);
    conv_split_f16<<<(QKVO * HH / 4 + 255) / 256, 256>>>(wqkv, wqh, wql, QKVO * HH / 4);
    conv_f16<<<(HH * HH / 4 + 255) / 256, 256>>>(wo, wof, HH * HH / 4);

    // 1a) QKV projection, Q columns [0,3584): f16 1-pass
    tc_gemm<1,1><<<dim3(28, TT / 128), 256, gemm_smem>>>(af, wqh, wqh, bqkv, qkv_ptr, QKVO);
    // 1b) QKV projection, KV columns [3584,4608): f16 2-pass (weights compensated)
    tc_gemm<1,2><<<dim3(8, TT / 128), 256, gemm_smem>>>(
        af, wqh + (size_t)3584 * KT, wql + (size_t)3584 * KT,
        bqkv + 3584, qkv_ptr + 3584, QKVO);

    // 2) copy input cache into output cache region
    cudaMemcpyAsync(cache_out, kvc, (size_t)2 * CACHE_HALF * sizeof(float),
                    cudaMemcpyDeviceToDevice);

    // 3) RoPE + scatter + f16 operand prep
    {
        const int total = TT * 36 * 64;
        rope_scatter<<<(total + 255) / 256, 256>>>(positions, slot_mapping, cache_out);
    }

    // 4) f16 tensor-core causal GQA flash attention -> ctx f16
    attn_fwd_tc<<<dim3(SEQ / 64, NHEADS, NBATCH), 128, attn_smem>>>(cf);

    // 5) output projection: f16 1-pass
    tc_gemm<0,1><<<dim3(28, TT / 128), 256, gemm_smem>>>(cf, wof, wof, nullptr, out, HH);

    (void)out_size;
}

// round 16
// speedup vs baseline: 7.6484x; 1.0041x over previous
#include <cuda_runtime.h>
#include <cuda_bf16.h>
#include <cuda_fp16.h>
#include <math.h>
#include <stdint.h>

// ---------------- problem constants ----------------
#define TT      4096            // B*S tokens
#define HH      3584            // hidden
#define NHEADS  28
#define NKVH    4
#define GROUP   7
#define DH      128
#define QKVO    4608            // (28 + 2*4) * 128
#define SEQ     1024
#define NBATCH  4
#define KROW    512             // NKV*D, cache row per slot
#define CACHE_HALF 4194304      // NB*BS*NKV*D
#define OUT_ELEMS  14680064     // TT*HH
#define SCALE   0.088388347648318447f   // 1/sqrt(128)
#define KT      3584            // GEMM K (both projections)
#define PASSLEN64 (KT / 64)     // 56 k-stages of 64 per pass

// ---------------- scratch (device globals; no allocation) ----------------
__device__ float  g_qkv[(size_t)TT * QKVO];
__device__ __half g_af[(size_t)TT * HH];        // hidden f16
__device__ __half g_wqh[(size_t)QKVO * HH];     // w_qkv f16 hi
__device__ __half g_wql[(size_t)QKVO * HH];     // w_qkv f16 lo (used for KV rows)
__device__ __half g_wof[(size_t)HH * HH];       // w_o f16
__device__ __half g_cf[(size_t)TT * HH];        // ctx f16 (written by attention)
__device__ __half g_qf[(size_t)TT * HH];        // rope'd Q f16
__device__ __half g_kf[(size_t)TT * KROW];      // rope'd K f16
__device__ __half g_vf[(size_t)TT * KROW];      // V f16

// ---------------- PTX helpers (baseline features only) ----------------
__device__ __forceinline__ uint32_t smem_to_u32(const void* p) {
    uint32_t a;
    asm("{ .reg .u64 t; cvta.to.shared.u64 t, %1; cvt.u32.u64 %0, t; }" : "=r"(a) : "l"(p));
    return a;
}
__device__ __forceinline__ void cpasync16(uint32_t dst, const void* src) {
    asm volatile("cp.async.cg.shared.global [%0], [%1], 16;" :: "r"(dst), "l"(src));
}
#define CP_COMMIT() asm volatile("cp.async.commit_group;" ::: "memory")
#define CP_WAIT1()  asm volatile("cp.async.wait_group 1;" ::: "memory")
#define CP_WAIT0()  asm volatile("cp.async.wait_group 0;" ::: "memory")

__device__ __forceinline__ void ldsm4(uint32_t& r0, uint32_t& r1, uint32_t& r2, uint32_t& r3,
                                      uint32_t a) {
    asm volatile("ldmatrix.sync.aligned.m8n8.x4.shared.b16 {%0,%1,%2,%3}, [%4];"
                 : "=r"(r0), "=r"(r1), "=r"(r2), "=r"(r3) : "r"(a));
}
__device__ __forceinline__ void ldsm4t(uint32_t& r0, uint32_t& r1, uint32_t& r2, uint32_t& r3,
                                       uint32_t a) {
    asm volatile("ldmatrix.sync.aligned.m8n8.x4.trans.shared.b16 {%0,%1,%2,%3}, [%4];"
                 : "=r"(r0), "=r"(r1), "=r"(r2), "=r"(r3) : "r"(a));
}
__device__ __forceinline__ void mma_f16(float* c, const uint32_t* a, uint32_t b0, uint32_t b1) {
    asm volatile("mma.sync.aligned.m16n8k16.row.col.f32.f16.f16.f32 "
                 "{%0,%1,%2,%3}, {%4,%5,%6,%7}, {%8,%9}, {%0,%1,%2,%3};"
                 : "+f"(c[0]), "+f"(c[1]), "+f"(c[2]), "+f"(c[3])
                 : "r"(a[0]), "r"(a[1]), "r"(a[2]), "r"(a[3]), "r"(b0), "r"(b1));
}
__device__ __forceinline__ float ex2f(float x) {
    float y; asm("ex2.approx.ftz.f32 %0, %1;" : "=f"(y) : "f"(x)); return y;
}

// 128B-row tile swizzle (GEMM BK=64: 64 f16/row, 8 chunks of 16B)
__device__ __forceinline__ uint32_t swz128(int row, int chunk) {
    return (uint32_t)(row * 128 + ((chunk ^ (row & 7)) << 4));
}
// 256B-row tile swizzle (attention, 128 f16/row, 16 chunks of 16B)
__device__ __forceinline__ uint32_t swz256(int row, int chunk) {
    return (uint32_t)(row * 256 + ((chunk ^ (row & 7)) << 4));
}

// =====================================================================
// fp32 -> f16 single convert
// =====================================================================
__global__ void conv_f16(const float* __restrict__ x, __half* __restrict__ o, int n4)
{
    const int i = blockIdx.x * blockDim.x + threadIdx.x;
    if (i >= n4) return;
    const float4 v = ((const float4*)x)[i];
    __half2* O = (__half2*)(o + (size_t)i * 4);
    O[0] = __floats2half2_rn(v.x, v.y);
    O[1] = __floats2half2_rn(v.z, v.w);
}

// fp32 -> f16 hi + f16 lo split
__global__ void conv_split_f16(const float* __restrict__ x,
                               __half* __restrict__ hi, __half* __restrict__ lo, int n4)
{
    const int i = blockIdx.x * blockDim.x + threadIdx.x;
    if (i >= n4) return;
    const float4 v = ((const float4*)x)[i];
    __half h0 = __float2half_rn(v.x), h1 = __float2half_rn(v.y);
    __half h2 = __float2half_rn(v.z), h3 = __float2half_rn(v.w);
    __half2* H = (__half2*)(hi + (size_t)i * 4);
    __half2* L = (__half2*)(lo + (size_t)i * 4);
    H[0] = __half2(h0, h1); H[1] = __half2(h2, h3);
    L[0] = __floats2half2_rn(v.x - __half2float(h0), v.y - __half2float(h1));
    L[1] = __floats2half2_rn(v.z - __half2float(h2), v.w - __half2float(h3));
}

// =====================================================================
// HMMA f16 GEMM  C[M,*] = A[M,KT]*B[*,KT]^T (+bias)   (unchanged)
// =====================================================================
template<int BIAS, int NPASS>
__global__ void __launch_bounds__(256, 2) tc_gemm(const __half* __restrict__ A,
                                                  const __half* __restrict__ Bh,
                                                  const __half* __restrict__ Bl,
                                                  const float* __restrict__ bias,
                                                  float* __restrict__ C, int Nt)
{
    extern __shared__ __align__(1024) char smem[];   // 3 stages x (A 16K + B 16K)
    const uint32_t smem_u = smem_to_u32(smem);
    const int KSTEPS = NPASS * PASSLEN64;

    const int tid  = threadIdx.x;
    const int wid  = tid >> 5;
    const int lane = tid & 31;
    const int wm   = wid & 3;
    const int wn   = wid >> 2;
    const int n0   = blockIdx.x * 128;
    const int m0   = blockIdx.y * 128;

    int lrow[4]; uint32_t soff[4];
#pragma unroll
    for (int i = 0; i < 4; i++) {
        const int q = tid + 256 * i;
        lrow[i] = q >> 3;
        soff[i] = swz128(q >> 3, q & 7);
    }
    const int lchunk = tid & 7;

    const int g = lane >> 3, j = lane & 7;
    uint32_t a_off[2][4];
#pragma unroll
    for (int mt = 0; mt < 2; mt++)
#pragma unroll
        for (int kc = 0; kc < 4; kc++) {
            const int row = wm * 32 + mt * 16 + (g & 1) * 8 + j;
            a_off[mt][kc] = swz128(row, kc * 2 + (g >> 1));
        }
    uint32_t b_off[4][4];
#pragma unroll
    for (int nt = 0; nt < 4; nt++)
#pragma unroll
        for (int kc = 0; kc < 4; kc++) {
            const int row = wn * 64 + nt * 16 + (g >> 1) * 8 + j;
            b_off[nt][kc] = swz128(row, kc * 2 + (g & 1));
        }

    float acc[2][8][4];
#pragma unroll
    for (int mi = 0; mi < 2; mi++)
#pragma unroll
        for (int ni = 0; ni < 8; ni++)
#pragma unroll
            for (int k = 0; k < 4; k++) acc[mi][ni][k] = 0.f;

    auto load_stage = [&](int s, int buf) {
        const int pass = s / PASSLEN64;
        const int k0   = (s % PASSLEN64) * 64;
        const __half* Bp = (NPASS == 2 && pass == 1) ? Bl : Bh;
        const uint32_t Au = smem_u + buf * 32768;
        const uint32_t Bu = Au + 16384;
#pragma unroll
        for (int i = 0; i < 4; i++) {
            cpasync16(Au + soff[i], A  + (size_t)(m0 + lrow[i]) * KT + k0 + lchunk * 8);
            cpasync16(Bu + soff[i], Bp + (size_t)(n0 + lrow[i]) * KT + k0 + lchunk * 8);
        }
    };

    load_stage(0, 0); CP_COMMIT();
    load_stage(1, 1); CP_COMMIT();

#pragma unroll 1
    for (int s = 0; s < KSTEPS; s++) {
        CP_WAIT1();
        __syncthreads();
        const int buf = s % 3;
        if (s + 2 < KSTEPS) load_stage(s + 2, (s + 2) % 3);
        CP_COMMIT();

        const uint32_t Au = smem_u + buf * 32768;
        const uint32_t Bu = Au + 16384;
#pragma unroll
        for (int kc = 0; kc < 4; kc++) {
            uint32_t a[2][4];
            ldsm4(a[0][0], a[0][1], a[0][2], a[0][3], Au + a_off[0][kc]);
            ldsm4(a[1][0], a[1][1], a[1][2], a[1][3], Au + a_off[1][kc]);
            uint32_t b[8][2];
#pragma unroll
            for (int nt = 0; nt < 4; nt++)
                ldsm4(b[2 * nt][0], b[2 * nt][1], b[2 * nt + 1][0], b[2 * nt + 1][1],
                      Bu + b_off[nt][kc]);
#pragma unroll
            for (int mi = 0; mi < 2; mi++)
#pragma unroll
                for (int ni = 0; ni < 8; ni++)
                    mma_f16(acc[mi][ni], a[mi], b[ni][0], b[ni][1]);
        }
    }

    const int r0 = m0 + wm * 32 + (lane >> 2);
    const int c0 = n0 + wn * 64 + (lane & 3) * 2;
#pragma unroll
    for (int mi = 0; mi < 2; mi++)
#pragma unroll
        for (int ni = 0; ni < 8; ni++) {
            const int row = r0 + mi * 16;
            const int col = c0 + ni * 8;
            float b0 = 0.f, b1 = 0.f;
            if (BIAS) { b0 = bias[col]; b1 = bias[col + 1]; }
            *(float2*)&C[(size_t)row * Nt + col] =
                make_float2(acc[mi][ni][0] + b0, acc[mi][ni][1] + b1);
            *(float2*)&C[(size_t)(row + 8) * Nt + col] =
                make_float2(acc[mi][ni][2] + b0, acc[mi][ni][3] + b1);
        }
}

// =====================================================================
// RoPE: q -> f16 scratch; k -> fp32 cache + f16; v -> fp32 cache + f16
// =====================================================================
__global__ void rope_scatter(const int* __restrict__ positions,
                             const int* __restrict__ slot_mapping,
                             float* __restrict__ cache_out)
{
    const int idx = blockIdx.x * blockDim.x + threadIdx.x;
    const int total = TT * 36 * 64;
    if (idx >= total) return;
    const int i  = idx & 63;
    const int hh = (idx >> 6) % 36;
    const int t  = idx / (36 * 64);

    if (hh < 32) {
        const float pos = (float)positions[t];
        const float inv = exp2f(-(float)i * (13.287712379549449f / 64.0f));
        const float ang = pos * inv;
        float s, c;
        sincosf(ang, &s, &c);
        if (hh < 28) {
            const float* p = g_qkv + (size_t)t * QKVO + hh * DH;
            const float x1 = p[i], x2 = p[i + 64];
            const size_t o = (size_t)t * HH + hh * DH;
            g_qf[o + i]      = __float2half_rn(x1 * c - x2 * s);
            g_qf[o + i + 64] = __float2half_rn(x2 * c + x1 * s);
        } else {
            const int kvh = hh - 28;
            const float* p = g_qkv + (size_t)t * QKVO + NHEADS * DH + kvh * DH;
            const float x1 = p[i], x2 = p[i + 64];
            const float r1 = x1 * c - x2 * s;
            const float r2 = x2 * c + x1 * s;
            const size_t o = (size_t)t * KROW + kvh * DH;
            g_kf[o + i]      = __float2half_rn(r1);
            g_kf[o + i + 64] = __float2half_rn(r2);
            const int slot = slot_mapping[t];
            float* dst = cache_out + (size_t)slot * KROW + kvh * DH;
            dst[i]      = r1;
            dst[i + 64] = r2;
        }
    } else {
        const int kvh = hh - 32;
        const float* p = g_qkv + (size_t)t * QKVO + (NHEADS + NKVH) * DH + kvh * DH;
        const float v1 = p[i], v2 = p[i + 64];
        const size_t o = (size_t)t * KROW + kvh * DH;
        g_vf[o + i]      = __float2half_rn(v1);
        g_vf[o + i + 64] = __float2half_rn(v2);
        const int slot = slot_mapping[t];
        float* dst = cache_out + (size_t)CACHE_HALF + (size_t)slot * KROW + kvh * DH;
        dst[i]      = v1;
        dst[i + 64] = v2;
    }
}

// =====================================================================
// Tensor-core flash attention (causal, GQA), all-f16.
// CTA = 128 q rows x head x batch; 8 warps (256 thr); warp w -> rows w*16..+15.
// K/V double-buffered (2-stage cp.async ring). smem: Q 32K + 2x(K16K+V16K)=96K.
// =====================================================================
__global__ void __launch_bounds__(256) attn_fwd_tc(__half* __restrict__ cf_g)
{
    extern __shared__ __align__(1024) char smem[];
    const uint32_t su = smem_to_u32(smem);
    const uint32_t Qf = su;
    const uint32_t Kb[2] = { su + 32768, su + 49152 };
    const uint32_t Vb[2] = { su + 65536, su + 81920 };

    const int qt  = (gridDim.x - 1) - blockIdx.x;    // big tiles first
    const int h   = blockIdx.y, b = blockIdx.z;
    const int kvh = h / GROUP;
    const int tid = threadIdx.x, wid = tid >> 5, lane = tid & 31;
    const int g   = lane >> 3, jj = lane & 7;

    // ---- Q tile (128 rows, f16), loaded once ----
    {
        const int qrow = tid & 127, qc0 = (tid >> 7) * 8;
        const size_t t = (size_t)(b * SEQ + qt * 128 + qrow);
        const __half* gq = g_qf + t * HH + h * DH + qc0 * 8;
#pragma unroll
        for (int i = 0; i < 8; i++)
            cpasync16(Qf + swz256(qrow, qc0 + i), gq + i * 8);
    }

    // K/V loader: 64 rows x 16 chunks each for K and V (2048 chunks total);
    // 256 threads -> 4 K-chunks + 4 V-chunks per thread.
    const int krow = tid & 63;
    const int kc0  = (tid >> 6) * 4;          // {0,4,8,12}
    auto load_kv = [&](int j, int buf) {
        const size_t t = (size_t)(b * SEQ + j * 64 + krow);
        const __half* kk = g_kf + t * KROW + kvh * DH;
        const __half* vv = g_vf + t * KROW + kvh * DH;
#pragma unroll
        for (int i = 0; i < 4; i++) {
            cpasync16(Kb[buf] + swz256(krow, kc0 + i), kk + (kc0 + i) * 8);
            cpasync16(Vb[buf] + swz256(krow, kc0 + i), vv + (kc0 + i) * 8);
        }
    };

    load_kv(0, 0);
    CP_COMMIT();     // group: Q + K/V(0)

    const int arow = wid * 16 + (g & 1) * 8 + jj;   // A rows within 128-row Q tile
    const int acb  = g >> 1;
    const int brow = (g >> 1) * 8 + jj;             // B non-trans (K rows)
    const int bcb  = g & 1;
    const int vrow = (g & 1) * 8 + jj;              // B trans (V rows)
    const int vcb  = g >> 1;

    float O[16][4];
#pragma unroll
    for (int nt = 0; nt < 16; nt++)
#pragma unroll
        for (int k = 0; k < 4; k++) O[nt][k] = 0.f;
    float m0 = -1e30f, m1 = -1e30f, l0 = 0.f, l1 = 0.f;
    const float K1 = SCALE * 1.4426950408889634f;

    const int jmax = 2 * qt + 1;
    const int rg0  = qt * 128 + wid * 16 + (lane >> 2);   // global q row (group 0)

#pragma unroll 1
    for (int j = 0; j <= jmax; j++) {
        const int buf = j & 1;
        if (j < jmax) { load_kv(j + 1, buf ^ 1); CP_COMMIT(); CP_WAIT1(); }
        else          { CP_WAIT0(); }
        __syncthreads();

        // ---- QK^T (f16) ----
        float sa[8][4];
#pragma unroll
        for (int nt = 0; nt < 8; nt++)
#pragma unroll
            for (int k = 0; k < 4; k++) sa[nt][k] = 0.f;

#pragma unroll
        for (int ds = 0; ds < 8; ds++) {
            uint32_t qf[4];
            ldsm4(qf[0], qf[1], qf[2], qf[3], Qf + swz256(arow, ds * 2 + acb));
#pragma unroll
            for (int p = 0; p < 4; p++) {
                uint32_t k0, k1, k2, k3;
                ldsm4(k0, k1, k2, k3, Kb[buf] + swz256(p * 16 + brow, ds * 2 + bcb));
                mma_f16(sa[2 * p],     qf, k0, k1);
                mma_f16(sa[2 * p + 1], qf, k2, k3);
            }
        }

#pragma unroll
        for (int nt = 0; nt < 8; nt++)
#pragma unroll
            for (int k = 0; k < 4; k++) sa[nt][k] *= K1;

        // ---- causal mask (global indices) ----
        if (j * 64 + 63 > rg0) {
#pragma unroll
            for (int nt = 0; nt < 8; nt++) {
                const int cb = j * 64 + nt * 8 + 2 * (lane & 3);
                if (cb > rg0)         sa[nt][0] = -1e30f;
                if (cb + 1 > rg0)     sa[nt][1] = -1e30f;
                if (cb > rg0 + 8)     sa[nt][2] = -1e30f;
                if (cb + 1 > rg0 + 8) sa[nt][3] = -1e30f;
            }
        }

        // ---- online softmax ----
        float mt0 = -1e30f, mt1 = -1e30f;
#pragma unroll
        for (int nt = 0; nt < 8; nt++) {
            mt0 = fmaxf(mt0, fmaxf(sa[nt][0], sa[nt][1]));
            mt1 = fmaxf(mt1, fmaxf(sa[nt][2], sa[nt][3]));
        }
        mt0 = fmaxf(mt0, __shfl_xor_sync(0xffffffffu, mt0, 1));
        mt0 = fmaxf(mt0, __shfl_xor_sync(0xffffffffu, mt0, 2));
        mt1 = fmaxf(mt1, __shfl_xor_sync(0xffffffffu, mt1, 1));
        mt1 = fmaxf(mt1, __shfl_xor_sync(0xffffffffu, mt1, 2));
        const float mn0 = fmaxf(m0, mt0), mn1 = fmaxf(m1, mt1);
        const float cr0 = ex2f(m0 - mn0), cr1 = ex2f(m1 - mn1);
        m0 = mn0; m1 = mn1;

        uint32_t p2[2][8];
        float s0 = 0.f, s1 = 0.f;
#pragma unroll
        for (int nt = 0; nt < 8; nt++) {
            const float e0 = ex2f(sa[nt][0] - m0);
            const float e1 = ex2f(sa[nt][1] - m0);
            const float e2 = ex2f(sa[nt][2] - m1);
            const float e3 = ex2f(sa[nt][3] - m1);
            s0 += e0 + e1; s1 += e2 + e3;
            __half2 ha = __floats2half2_rn(e0, e1);
            __half2 hb = __floats2half2_rn(e2, e3);
            p2[0][nt] = *(uint32_t*)&ha;
            p2[1][nt] = *(uint32_t*)&hb;
        }
        s0 += __shfl_xor_sync(0xffffffffu, s0, 1);
        s0 += __shfl_xor_sync(0xffffffffu, s0, 2);
        s1 += __shfl_xor_sync(0xffffffffu, s1, 1);
        s1 += __shfl_xor_sync(0xffffffffu, s1, 2);
        l0 = l0 * cr0 + s0;
        l1 = l1 * cr1 + s1;
#pragma unroll
        for (int nt = 0; nt < 16; nt++) {
            O[nt][0] *= cr0; O[nt][1] *= cr0;
            O[nt][2] *= cr1; O[nt][3] *= cr1;
        }

        // ---- P @ V (f16) ----
#pragma unroll
        for (int ks = 0; ks < 4; ks++) {
            uint32_t af[4] = {p2[0][2 * ks], p2[1][2 * ks],
                              p2[0][2 * ks + 1], p2[1][2 * ks + 1]};
#pragma unroll
            for (int p = 0; p < 8; p++) {
                uint32_t v0, v1, v2, v3;
                ldsm4t(v0, v1, v2, v3, Vb[buf] + swz256(ks * 16 + vrow, p * 2 + vcb));
                mma_f16(O[2 * p],     af, v0, v1);
                mma_f16(O[2 * p + 1], af, v2, v3);
            }
        }
        __syncthreads();   // all reads of buf done before it is re-filled
    }

    // ---- epilogue: normalize, store f16 ctx ----
    const float il0 = 1.f / l0, il1 = 1.f / l1;
    const size_t t0 = (size_t)(b * SEQ + rg0);     // rg0 already includes qt*128
    const size_t t1 = t0 + 8;
#pragma unroll
    for (int nt = 0; nt < 16; nt++) {
        const int d = h * DH + nt * 8 + 2 * (lane & 3);
        *(__half2*)&cf_g[t0 * HH + d] = __floats2half2_rn(O[nt][0] * il0, O[nt][1] * il0);
        *(__half2*)&cf_g[t1 * HH + d] = __floats2half2_rn(O[nt][2] * il1, O[nt][3] * il1);
    }
}

// =====================================================================
// launch
// =====================================================================
extern "C" void kernel_launch(void* const* d_in, const int* in_sizes, int n_in,
                              void* d_out, int out_size)
{
    const float* hs = nullptr;
    const float* wqkv = nullptr;
    const float* bqkv = nullptr;
    const float* wo = nullptr;
    const float* kvc = nullptr;
    const int* positions = nullptr;
    const int* slot_mapping = nullptr;

    for (int i = 0; i < n_in; i++) {
        switch (in_sizes[i]) {
            case 14680064: hs   = (const float*)d_in[i]; break;
            case 16515072: wqkv = (const float*)d_in[i]; break;
            case 4608:     bqkv = (const float*)d_in[i]; break;
            case 12845056: wo   = (const float*)d_in[i]; break;
            case 8388608:  kvc  = (const float*)d_in[i]; break;
            case 4096:
                if (!positions)         positions    = (const int*)d_in[i];
                else if (!slot_mapping) slot_mapping = (const int*)d_in[i];
                break;
            default: break;
        }
    }

    float* out       = (float*)d_out;
    float* cache_out = out + OUT_ELEMS;

    float* qkv_ptr;
    __half *af, *wqh, *wql, *wof, *cf;
    cudaGetSymbolAddress((void**)&qkv_ptr, g_qkv);
    cudaGetSymbolAddress((void**)&af, g_af);
    cudaGetSymbolAddress((void**)&wqh, g_wqh);
    cudaGetSymbolAddress((void**)&wql, g_wql);
    cudaGetSymbolAddress((void**)&wof, g_wof);
    cudaGetSymbolAddress((void**)&cf, g_cf);

    const int gemm_smem = 3 * 32768;   // 96KB
    cudaFuncSetAttribute(tc_gemm<1,1>, cudaFuncAttributeMaxDynamicSharedMemorySize, gemm_smem);
    cudaFuncSetAttribute(tc_gemm<1,2>, cudaFuncAttributeMaxDynamicSharedMemorySize, gemm_smem);
    cudaFuncSetAttribute(tc_gemm<0,1>, cudaFuncAttributeMaxDynamicSharedMemorySize, gemm_smem);
    const int attn_smem = 96 * 1024;   // Q 32K + 2x(K 16K + V 16K)
    cudaFuncSetAttribute(attn_fwd_tc, cudaFuncAttributeMaxDynamicSharedMemorySize, attn_smem);

    // 0) f16 conversions
    conv_f16<<<(TT * HH / 4 + 255) / 256, 256>>>(hs, af, TT * HH / 4);
    conv_split_f16<<<(QKVO * HH / 4 + 255) / 256, 256>>>(wqkv, wqh, wql, QKVO * HH / 4);
    conv_f16<<<(HH * HH / 4 + 255) / 256, 256>>>(wo, wof, HH * HH / 4);

    // 1a) QKV projection, Q columns [0,3584): f16 1-pass
    tc_gemm<1,1><<<dim3(28, TT / 128), 256, gemm_smem>>>(af, wqh, wqh, bqkv, qkv_ptr, QKVO);
    // 1b) QKV projection, KV columns [3584,4608): f16 2-pass (weights compensated)
    tc_gemm<1,2><<<dim3(8, TT / 128), 256, gemm_smem>>>(
        af, wqh + (size_t)3584 * KT, wql + (size_t)3584 * KT,
        bqkv + 3584, qkv_ptr + 3584, QKVO);

    // 2) copy input cache into output cache region
    cudaMemcpyAsync(cache_out, kvc, (size_t)2 * CACHE_HALF * sizeof(float),
                    cudaMemcpyDeviceToDevice);

    // 3) RoPE + scatter + f16 operand prep
    {
        const int total = TT * 36 * 64;
        rope_scatter<<<(total + 255) / 256, 256>>>(positions, slot_mapping, cache_out);
    }

    // 4) f16 tensor-core causal GQA flash attention (128-row CTAs, double-buffered)
    attn_fwd_tc<<<dim3(SEQ / 128, NHEADS, NBATCH), 256, attn_smem>>>(cf);

    // 5) output projection: f16 1-pass
    tc_gemm<0,1><<<dim3(28, TT / 128), 256, gemm_smem>>>(cf, wof, wof, nullptr, out, HH);

    (void)out_size;
}

// round 17
// speedup vs baseline: 7.8739x; 1.0295x over previous
#include <cuda_runtime.h>
#include <cuda_bf16.h>
#include <cuda_fp16.h>
#include <math.h>
#include <stdint.h>

// ---------------- problem constants ----------------
#define TT      4096            // B*S tokens
#define HH      3584            // hidden
#define NHEADS  28
#define NKVH    4
#define GROUP   7
#define DH      128
#define QKVO    4608            // (28 + 2*4) * 128
#define SEQ     1024
#define NBATCH  4
#define KROW    512             // NKV*D, cache row per slot
#define CACHE_HALF 4194304      // NB*BS*NKV*D
#define OUT_ELEMS  14680064     // TT*HH
#define SCALE   0.088388347648318447f   // 1/sqrt(128)
#define KT      3584            // GEMM K (both projections)
#define PASSLEN64 (KT / 64)     // 56 k-stages of 64 per pass

// ---------------- scratch (device globals; no allocation) ----------------
__device__ float  g_qkv[(size_t)TT * QKVO];
__device__ __half g_af[(size_t)TT * HH];        // hidden f16
__device__ __half g_wqh[(size_t)QKVO * HH];     // w_qkv f16 hi
__device__ __half g_wql[(size_t)QKVO * HH];     // w_qkv f16 lo (used for KV rows)
__device__ __half g_wof[(size_t)HH * HH];       // w_o f16
__device__ __half g_cf[(size_t)TT * HH];        // ctx f16 (written by attention)
__device__ __half g_qf[(size_t)TT * HH];        // rope'd Q f16
__device__ __half g_kf[(size_t)TT * KROW];      // rope'd K f16
__device__ __half g_vf[(size_t)TT * KROW];      // V f16
__device__ float2 g_rt[(size_t)TT * 64];        // rope cos/sin table [t][i]

// ---------------- PTX helpers (baseline features only) ----------------
__device__ __forceinline__ uint32_t smem_to_u32(const void* p) {
    uint32_t a;
    asm("{ .reg .u64 t; cvta.to.shared.u64 t, %1; cvt.u32.u64 %0, t; }" : "=r"(a) : "l"(p));
    return a;
}
__device__ __forceinline__ void cpasync16(uint32_t dst, const void* src) {
    asm volatile("cp.async.cg.shared.global [%0], [%1], 16;" :: "r"(dst), "l"(src));
}
#define CP_COMMIT() asm volatile("cp.async.commit_group;" ::: "memory")
#define CP_WAIT1()  asm volatile("cp.async.wait_group 1;" ::: "memory")
#define CP_WAIT0()  asm volatile("cp.async.wait_group 0;" ::: "memory")

__device__ __forceinline__ void ldsm4(uint32_t& r0, uint32_t& r1, uint32_t& r2, uint32_t& r3,
                                      uint32_t a) {
    asm volatile("ldmatrix.sync.aligned.m8n8.x4.shared.b16 {%0,%1,%2,%3}, [%4];"
                 : "=r"(r0), "=r"(r1), "=r"(r2), "=r"(r3) : "r"(a));
}
__device__ __forceinline__ void ldsm4t(uint32_t& r0, uint32_t& r1, uint32_t& r2, uint32_t& r3,
                                       uint32_t a) {
    asm volatile("ldmatrix.sync.aligned.m8n8.x4.trans.shared.b16 {%0,%1,%2,%3}, [%4];"
                 : "=r"(r0), "=r"(r1), "=r"(r2), "=r"(r3) : "r"(a));
}
__device__ __forceinline__ void mma_f16(float* c, const uint32_t* a, uint32_t b0, uint32_t b1) {
    asm volatile("mma.sync.aligned.m16n8k16.row.col.f32.f16.f16.f32 "
                 "{%0,%1,%2,%3}, {%4,%5,%6,%7}, {%8,%9}, {%0,%1,%2,%3};"
                 : "+f"(c[0]), "+f"(c[1]), "+f"(c[2]), "+f"(c[3])
                 : "r"(a[0]), "r"(a[1]), "r"(a[2]), "r"(a[3]), "r"(b0), "r"(b1));
}
__device__ __forceinline__ float ex2f(float x) {
    float y; asm("ex2.approx.ftz.f32 %0, %1;" : "=f"(y) : "f"(x)); return y;
}

// 128B-row tile swizzle (GEMM BK=64: 64 f16/row, 8 chunks of 16B)
__device__ __forceinline__ uint32_t swz128(int row, int chunk) {
    return (uint32_t)(row * 128 + ((chunk ^ (row & 7)) << 4));
}
// 256B-row tile swizzle (attention, 128 f16/row, 16 chunks of 16B)
__device__ __forceinline__ uint32_t swz256(int row, int chunk) {
    return (uint32_t)(row * 256 + ((chunk ^ (row & 7)) << 4));
}

// =====================================================================
// fp32 -> f16 single convert
// =====================================================================
__global__ void conv_f16(const float* __restrict__ x, __half* __restrict__ o, int n4)
{
    const int i = blockIdx.x * blockDim.x + threadIdx.x;
    if (i >= n4) return;
    const float4 v = ((const float4*)x)[i];
    __half2* O = (__half2*)(o + (size_t)i * 4);
    O[0] = __floats2half2_rn(v.x, v.y);
    O[1] = __floats2half2_rn(v.z, v.w);
}

// fp32 -> f16 hi + f16 lo split
__global__ void conv_split_f16(const float* __restrict__ x,
                               __half* __restrict__ hi, __half* __restrict__ lo, int n4)
{
    const int i = blockIdx.x * blockDim.x + threadIdx.x;
    if (i >= n4) return;
    const float4 v = ((const float4*)x)[i];
    __half h0 = __float2half_rn(v.x), h1 = __float2half_rn(v.y);
    __half h2 = __float2half_rn(v.z), h3 = __float2half_rn(v.w);
    __half2* H = (__half2*)(hi + (size_t)i * 4);
    __half2* L = (__half2*)(lo + (size_t)i * 4);
    H[0] = __half2(h0, h1); H[1] = __half2(h2, h3);
    L[0] = __floats2half2_rn(v.x - __half2float(h0), v.y - __half2float(h1));
    L[1] = __floats2half2_rn(v.z - __half2float(h2), v.w - __half2float(h3));
}

// =====================================================================
// rope cos/sin table: one sincosf per distinct (t, i) pair (identical math
// to the previous in-place computation -> bit-identical results)
// =====================================================================
__global__ void rope_table(const int* __restrict__ positions)
{
    const int idx = blockIdx.x * blockDim.x + threadIdx.x;
    if (idx >= TT * 64) return;
    const int t = idx >> 6, i = idx & 63;
    const float inv = exp2f(-(float)i * (13.287712379549449f / 64.0f));
    const float ang = (float)positions[t] * inv;
    float s, c;
    sincosf(ang, &s, &c);
    g_rt[idx] = make_float2(c, s);
}

// =====================================================================
// GEMM core (shared by merged QKV kernel and O-proj template).
// 128x128 CTA tile, 8 warps (4M x 2N), warp tile 32x64, BK=64,
// 3-stage cp.async pipeline. B error-compensation pass optional.
// =====================================================================
template<int BIAS>
__device__ __forceinline__ void gemm_body(const __half* __restrict__ A,
                                          const __half* __restrict__ Bh,
                                          const __half* __restrict__ Bl,
                                          const float* __restrict__ bias,
                                          float* __restrict__ C, int Nt,
                                          int m0, int n0, int npass, char* smem)
{
    const uint32_t smem_u = smem_to_u32(smem);
    const int KSTEPS = npass * PASSLEN64;

    const int tid  = threadIdx.x;
    const int wid  = tid >> 5;
    const int lane = tid & 31;
    const int wm   = wid & 3;
    const int wn   = wid >> 2;

    int lrow[4]; uint32_t soff[4];
#pragma unroll
    for (int i = 0; i < 4; i++) {
        const int q = tid + 256 * i;
        lrow[i] = q >> 3;
        soff[i] = swz128(q >> 3, q & 7);
    }
    const int lchunk = tid & 7;

    const int g = lane >> 3, j = lane & 7;
    uint32_t a_off[2][4];
#pragma unroll
    for (int mt = 0; mt < 2; mt++)
#pragma unroll
        for (int kc = 0; kc < 4; kc++) {
            const int row = wm * 32 + mt * 16 + (g & 1) * 8 + j;
            a_off[mt][kc] = swz128(row, kc * 2 + (g >> 1));
        }
    uint32_t b_off[4][4];
#pragma unroll
    for (int nt = 0; nt < 4; nt++)
#pragma unroll
        for (int kc = 0; kc < 4; kc++) {
            const int row = wn * 64 + nt * 16 + (g >> 1) * 8 + j;
            b_off[nt][kc] = swz128(row, kc * 2 + (g & 1));
        }

    float acc[2][8][4];
#pragma unroll
    for (int mi = 0; mi < 2; mi++)
#pragma unroll
        for (int ni = 0; ni < 8; ni++)
#pragma unroll
            for (int k = 0; k < 4; k++) acc[mi][ni][k] = 0.f;

    auto load_stage = [&](int s, int buf) {
        const int pass = s / PASSLEN64;
        const int k0   = (s % PASSLEN64) * 64;
        const __half* Bp = (pass == 1) ? Bl : Bh;
        const uint32_t Au = smem_u + buf * 32768;
        const uint32_t Bu = Au + 16384;
#pragma unroll
        for (int i = 0; i < 4; i++) {
            cpasync16(Au + soff[i], A  + (size_t)(m0 + lrow[i]) * KT + k0 + lchunk * 8);
            cpasync16(Bu + soff[i], Bp + (size_t)(n0 + lrow[i]) * KT + k0 + lchunk * 8);
        }
    };

    load_stage(0, 0); CP_COMMIT();
    load_stage(1, 1); CP_COMMIT();

#pragma unroll 1
    for (int s = 0; s < KSTEPS; s++) {
        CP_WAIT1();
        __syncthreads();
        const int buf = s % 3;
        if (s + 2 < KSTEPS) load_stage(s + 2, (s + 2) % 3);
        CP_COMMIT();

        const uint32_t Au = smem_u + buf * 32768;
        const uint32_t Bu = Au + 16384;
#pragma unroll
        for (int kc = 0; kc < 4; kc++) {
            uint32_t a[2][4];
            ldsm4(a[0][0], a[0][1], a[0][2], a[0][3], Au + a_off[0][kc]);
            ldsm4(a[1][0], a[1][1], a[1][2], a[1][3], Au + a_off[1][kc]);
            uint32_t b[8][2];
#pragma unroll
            for (int nt = 0; nt < 4; nt++)
                ldsm4(b[2 * nt][0], b[2 * nt][1], b[2 * nt + 1][0], b[2 * nt + 1][1],
                      Bu + b_off[nt][kc]);
#pragma unroll
            for (int mi = 0; mi < 2; mi++)
#pragma unroll
                for (int ni = 0; ni < 8; ni++)
                    mma_f16(acc[mi][ni], a[mi], b[ni][0], b[ni][1]);
        }
    }

    const int r0 = m0 + wm * 32 + (lane >> 2);
    const int c0 = n0 + wn * 64 + (lane & 3) * 2;
#pragma unroll
    for (int mi = 0; mi < 2; mi++)
#pragma unroll
        for (int ni = 0; ni < 8; ni++) {
            const int row = r0 + mi * 16;
            const int col = c0 + ni * 8;
            float b0 = 0.f, b1 = 0.f;
            if (BIAS) { b0 = bias[col]; b1 = bias[col + 1]; }
            *(float2*)&C[(size_t)row * Nt + col] =
                make_float2(acc[mi][ni][0] + b0, acc[mi][ni][1] + b1);
            *(float2*)&C[(size_t)(row + 8) * Nt + col] =
                make_float2(acc[mi][ni][2] + b0, acc[mi][ni][3] + b1);
        }
}

// Merged QKV projection: blocks [0,256) = KV columns (2-pass, long jobs first),
// blocks [256,1152) = Q columns (1-pass).
__global__ void __launch_bounds__(256, 2) qkv_gemm(const __half* __restrict__ A,
                                                   const __half* __restrict__ Bh,
                                                   const __half* __restrict__ Bl,
                                                   const float* __restrict__ bias,
                                                   float* __restrict__ C)
{
    extern __shared__ __align__(1024) char smem[];
    const int bx = blockIdx.x;
    int m0, n0, npass;
    if (bx < 256) {            // KV part: n in [3584, 4608)
        npass = 2;
        n0 = 3584 + (bx & 7) * 128;
        m0 = (bx >> 3) * 128;
    } else {                   // Q part: n in [0, 3584)
        const int t = bx - 256;
        npass = 1;
        n0 = (t % 28) * 128;
        m0 = (t / 28) * 128;
    }
    gemm_body<1>(A, Bh, Bl, bias, C, QKVO, m0, n0, npass, smem);
}

// O-projection (1-pass, no bias)
__global__ void __launch_bounds__(256, 2) o_gemm(const __half* __restrict__ A,
                                                 const __half* __restrict__ Bh,
                                                 float* __restrict__ C)
{
    extern __shared__ __align__(1024) char smem[];
    const int n0 = blockIdx.x * 128;
    const int m0 = blockIdx.y * 128;
    gemm_body<0>(A, Bh, Bh, nullptr, C, HH, m0, n0, 1, smem);
}

// =====================================================================
// RoPE (table-driven): q -> f16 scratch; k -> fp32 cache + f16;
//                      v -> fp32 cache + f16
// =====================================================================
__global__ void rope_scatter(const int* __restrict__ slot_mapping,
                             float* __restrict__ cache_out)
{
    const int idx = blockIdx.x * blockDim.x + threadIdx.x;
    const int total = TT * 36 * 64;
    if (idx >= total) return;
    const int i  = idx & 63;
    const int hh = (idx >> 6) % 36;
    const int t  = idx / (36 * 64);

    if (hh < 32) {
        const float2 cs = g_rt[(t << 6) | i];
        const float c = cs.x, s = cs.y;
        if (hh < 28) {
            const float* p = g_qkv + (size_t)t * QKVO + hh * DH;
            const float x1 = p[i], x2 = p[i + 64];
            const size_t o = (size_t)t * HH + hh * DH;
            g_qf[o + i]      = __float2half_rn(x1 * c - x2 * s);
            g_qf[o + i + 64] = __float2half_rn(x2 * c + x1 * s);
        } else {
            const int kvh = hh - 28;
            const float* p = g_qkv + (size_t)t * QKVO + NHEADS * DH + kvh * DH;
            const float x1 = p[i], x2 = p[i + 64];
            const float r1 = x1 * c - x2 * s;
            const float r2 = x2 * c + x1 * s;
            const size_t o = (size_t)t * KROW + kvh * DH;
            g_kf[o + i]      = __float2half_rn(r1);
            g_kf[o + i + 64] = __float2half_rn(r2);
            const int slot = slot_mapping[t];
            float* dst = cache_out + (size_t)slot * KROW + kvh * DH;
            dst[i]      = r1;
            dst[i + 64] = r2;
        }
    } else {
        const int kvh = hh - 32;
        const float* p = g_qkv + (size_t)t * QKVO + (NHEADS + NKVH) * DH + kvh * DH;
        const float v1 = p[i], v2 = p[i + 64];
        const size_t o = (size_t)t * KROW + kvh * DH;
        g_vf[o + i]      = __float2half_rn(v1);
        g_vf[o + i + 64] = __float2half_rn(v2);
        const int slot = slot_mapping[t];
        float* dst = cache_out + (size_t)CACHE_HALF + (size_t)slot * KROW + kvh * DH;
        dst[i]      = v1;
        dst[i + 64] = v2;
    }
}

// =====================================================================
// Tensor-core flash attention (causal, GQA), all-f16.  (unchanged R16)
// CTA = 128 q rows x head x batch; 8 warps; K/V double-buffered; 96KB smem.
// =====================================================================
__global__ void __launch_bounds__(256) attn_fwd_tc(__half* __restrict__ cf_g)
{
    extern __shared__ __align__(1024) char smem[];
    const uint32_t su = smem_to_u32(smem);
    const uint32_t Qf = su;
    const uint32_t Kb[2] = { su + 32768, su + 49152 };
    const uint32_t Vb[2] = { su + 65536, su + 81920 };

    const int qt  = (gridDim.x - 1) - blockIdx.x;    // big tiles first
    const int h   = blockIdx.y, b = blockIdx.z;
    const int kvh = h / GROUP;
    const int tid = threadIdx.x, wid = tid >> 5, lane = tid & 31;
    const int g   = lane >> 3, jj = lane & 7;

    // ---- Q tile (128 rows, f16), loaded once ----
    {
        const int qrow = tid & 127, qc0 = (tid >> 7) * 8;
        const size_t t = (size_t)(b * SEQ + qt * 128 + qrow);
        const __half* gq = g_qf + t * HH + h * DH + qc0 * 8;
#pragma unroll
        for (int i = 0; i < 8; i++)
            cpasync16(Qf + swz256(qrow, qc0 + i), gq + i * 8);
    }

    // K/V loader: 64 rows x 16 chunks each; 4 K-chunks + 4 V-chunks per thread.
    const int krow = tid & 63;
    const int kc0  = (tid >> 6) * 4;          // {0,4,8,12}
    auto load_kv = [&](int j, int buf) {
        const size_t t = (size_t)(b * SEQ + j * 64 + krow);
        const __half* kk = g_kf + t * KROW + kvh * DH;
        const __half* vv = g_vf + t * KROW + kvh * DH;
#pragma unroll
        for (int i = 0; i < 4; i++) {
            cpasync16(Kb[buf] + swz256(krow, kc0 + i), kk + (kc0 + i) * 8);
            cpasync16(Vb[buf] + swz256(krow, kc0 + i), vv + (kc0 + i) * 8);
        }
    };

    load_kv(0, 0);
    CP_COMMIT();     // group: Q + K/V(0)

    const int arow = wid * 16 + (g & 1) * 8 + jj;
    const int acb  = g >> 1;
    const int brow = (g >> 1) * 8 + jj;
    const int bcb  = g & 1;
    const int vrow = (g & 1) * 8 + jj;
    const int vcb  = g >> 1;

    float O[16][4];
#pragma unroll
    for (int nt = 0; nt < 16; nt++)
#pragma unroll
        for (int k = 0; k < 4; k++) O[nt][k] = 0.f;
    float m0 = -1e30f, m1 = -1e30f, l0 = 0.f, l1 = 0.f;
    const float K1 = SCALE * 1.4426950408889634f;

    const int jmax = 2 * qt + 1;
    const int rg0  = qt * 128 + wid * 16 + (lane >> 2);

#pragma unroll 1
    for (int j = 0; j <= jmax; j++) {
        const int buf = j & 1;
        if (j < jmax) { load_kv(j + 1, buf ^ 1); CP_COMMIT(); CP_WAIT1(); }
        else          { CP_WAIT0(); }
        __syncthreads();

        // ---- QK^T (f16) ----
        float sa[8][4];
#pragma unroll
        for (int nt = 0; nt < 8; nt++)
#pragma unroll
            for (int k = 0; k < 4; k++) sa[nt][k] = 0.f;

#pragma unroll
        for (int ds = 0; ds < 8; ds++) {
            uint32_t qf[4];
            ldsm4(qf[0], qf[1], qf[2], qf[3], Qf + swz256(arow, ds * 2 + acb));
#pragma unroll
            for (int p = 0; p < 4; p++) {
                uint32_t k0, k1, k2, k3;
                ldsm4(k0, k1, k2, k3, Kb[buf] + swz256(p * 16 + brow, ds * 2 + bcb));
                mma_f16(sa[2 * p],     qf, k0, k1);
                mma_f16(sa[2 * p + 1], qf, k2, k3);
            }
        }

#pragma unroll
        for (int nt = 0; nt < 8; nt++)
#pragma unroll
            for (int k = 0; k < 4; k++) sa[nt][k] *= K1;

        // ---- causal mask (global indices) ----
        if (j * 64 + 63 > rg0) {
#pragma unroll
            for (int nt = 0; nt < 8; nt++) {
                const int cb = j * 64 + nt * 8 + 2 * (lane & 3);
                if (cb > rg0)         sa[nt][0] = -1e30f;
                if (cb + 1 > rg0)     sa[nt][1] = -1e30f;
                if (cb > rg0 + 8)     sa[nt][2] = -1e30f;
                if (cb + 1 > rg0 + 8) sa[nt][3] = -1e30f;
            }
        }

        // ---- online softmax ----
        float mt0 = -1e30f, mt1 = -1e30f;
#pragma unroll
        for (int nt = 0; nt < 8; nt++) {
            mt0 = fmaxf(mt0, fmaxf(sa[nt][0], sa[nt][1]));
            mt1 = fmaxf(mt1, fmaxf(sa[nt][2], sa[nt][3]));
        }
        mt0 = fmaxf(mt0, __shfl_xor_sync(0xffffffffu, mt0, 1));
        mt0 = fmaxf(mt0, __shfl_xor_sync(0xffffffffu, mt0, 2));
        mt1 = fmaxf(mt1, __shfl_xor_sync(0xffffffffu, mt1, 1));
        mt1 = fmaxf(mt1, __shfl_xor_sync(0xffffffffu, mt1, 2));
        const float mn0 = fmaxf(m0, mt0), mn1 = fmaxf(m1, mt1);
        const float cr0 = ex2f(m0 - mn0), cr1 = ex2f(m1 - mn1);
        m0 = mn0; m1 = mn1;

        uint32_t p2[2][8];
        float s0 = 0.f, s1 = 0.f;
#pragma unroll
        for (int nt = 0; nt < 8; nt++) {
            const float e0 = ex2f(sa[nt][0] - m0);
            const float e1 = ex2f(sa[nt][1] - m0);
            const float e2 = ex2f(sa[nt][2] - m1);
            const float e3 = ex2f(sa[nt][3] - m1);
            s0 += e0 + e1; s1 += e2 + e3;
            __half2 ha = __floats2half2_rn(e0, e1);
            __half2 hb = __floats2half2_rn(e2, e3);
            p2[0][nt] = *(uint32_t*)&ha;
            p2[1][nt] = *(uint32_t*)&hb;
        }
        s0 += __shfl_xor_sync(0xffffffffu, s0, 1);
        s0 += __shfl_xor_sync(0xffffffffu, s0, 2);
        s1 += __shfl_xor_sync(0xffffffffu, s1, 1);
        s1 += __shfl_xor_sync(0xffffffffu, s1, 2);
        l0 = l0 * cr0 + s0;
        l1 = l1 * cr1 + s1;
#pragma unroll
        for (int nt = 0; nt < 16; nt++) {
            O[nt][0] *= cr0; O[nt][1] *= cr0;
            O[nt][2] *= cr1; O[nt][3] *= cr1;
        }

        // ---- P @ V (f16) ----
#pragma unroll
        for (int ks = 0; ks < 4; ks++) {
            uint32_t af[4] = {p2[0][2 * ks], p2[1][2 * ks],
                              p2[0][2 * ks + 1], p2[1][2 * ks + 1]};
#pragma unroll
            for (int p = 0; p < 8; p++) {
                uint32_t v0, v1, v2, v3;
                ldsm4t(v0, v1, v2, v3, Vb[buf] + swz256(ks * 16 + vrow, p * 2 + vcb));
                mma_f16(O[2 * p],     af, v0, v1);
                mma_f16(O[2 * p + 1], af, v2, v3);
            }
        }
        __syncthreads();   // all reads of buf done before it is re-filled
    }

    // ---- epilogue: normalize, store f16 ctx ----
    const float il0 = 1.f / l0, il1 = 1.f / l1;
    const size_t t0 = (size_t)(b * SEQ + rg0);
    const size_t t1 = t0 + 8;
#pragma unroll
    for (int nt = 0; nt < 16; nt++) {
        const int d = h * DH + nt * 8 + 2 * (lane & 3);
        *(__half2*)&cf_g[t0 * HH + d] = __floats2half2_rn(O[nt][0] * il0, O[nt][1] * il0);
        *(__half2*)&cf_g[t1 * HH + d] = __floats2half2_rn(O[nt][2] * il1, O[nt][3] * il1);
    }
}

// =====================================================================
// launch
// =====================================================================
extern "C" void kernel_launch(void* const* d_in, const int* in_sizes, int n_in,
                              void* d_out, int out_size)
{
    const float* hs = nullptr;
    const float* wqkv = nullptr;
    const float* bqkv = nullptr;
    const float* wo = nullptr;
    const float* kvc = nullptr;
    const int* positions = nullptr;
    const int* slot_mapping = nullptr;

    for (int i = 0; i < n_in; i++) {
        switch (in_sizes[i]) {
            case 14680064: hs   = (const float*)d_in[i]; break;
            case 16515072: wqkv = (const float*)d_in[i]; break;
            case 4608:     bqkv = (const float*)d_in[i]; break;
            case 12845056: wo   = (const float*)d_in[i]; break;
            case 8388608:  kvc  = (const float*)d_in[i]; break;
            case 4096:
                if (!positions)         positions    = (const int*)d_in[i];
                else if (!slot_mapping) slot_mapping = (const int*)d_in[i];
                break;
            default: break;
        }
    }

    float* out       = (float*)d_out;
    float* cache_out = out + OUT_ELEMS;

    float* qkv_ptr;
    __half *af, *wqh, *wql, *wof, *cf;
    cudaGetSymbolAddress((void**)&qkv_ptr, g_qkv);
    cudaGetSymbolAddress((void**)&af, g_af);
    cudaGetSymbolAddress((void**)&wqh, g_wqh);
    cudaGetSymbolAddress((void**)&wql, g_wql);
    cudaGetSymbolAddress((void**)&wof, g_wof);
    cudaGetSymbolAddress((void**)&cf, g_cf);

    const int gemm_smem = 3 * 32768;   // 96KB
    cudaFuncSetAttribute(qkv_gemm, cudaFuncAttributeMaxDynamicSharedMemorySize, gemm_smem);
    cudaFuncSetAttribute(o_gemm,   cudaFuncAttributeMaxDynamicSharedMemorySize, gemm_smem);
    const int attn_smem = 96 * 1024;   // Q 32K + 2x(K 16K + V 16K)
    cudaFuncSetAttribute(attn_fwd_tc, cudaFuncAttributeMaxDynamicSharedMemorySize, attn_smem);

    // 0) f16 conversions + rope table
    conv_f16<<<(TT * HH / 4 + 255) / 256, 256>>>(hs, af, TT * HH / 4);
    conv_split_f16<<<(QKVO * HH / 4 + 255) / 256, 256>>>(wqkv, wqh, wql, QKVO * HH / 4);
    conv_f16<<<(HH * HH / 4 + 255) / 256, 256>>>(wo, wof, HH * HH / 4);
    rope_table<<<(TT * 64 + 255) / 256, 256>>>(positions);

    // 1) merged QKV projection (KV 2-pass blocks first, Q 1-pass backfill)
    qkv_gemm<<<1152, 256, gemm_smem>>>(af, wqh, wql, bqkv, qkv_ptr);

    // 2) copy input cache into output cache region
    cudaMemcpyAsync(cache_out, kvc, (size_t)2 * CACHE_HALF * sizeof(float),
                    cudaMemcpyDeviceToDevice);

    // 3) RoPE (table-driven) + scatter + f16 operand prep
    {
        const int total = TT * 36 * 64;
        rope_scatter<<<(total + 255) / 256, 256>>>(slot_mapping, cache_out);
    }

    // 4) f16 tensor-core causal GQA flash attention (128-row CTAs, double-buffered)
    attn_fwd_tc<<<dim3(SEQ / 128, NHEADS, NBATCH), 256, attn_smem>>>(cf);

    // 5) output projection: f16 1-pass
    o_gemm<<<dim3(28, TT / 128), 256, gemm_smem>>>(cf, wof, out);

    (void)out_size;
}